// round 11
// baseline (speedup 1.0000x reference)
#include <cuda_runtime.h>
#include <cuda_bf16.h>
#include <cstdint>
#include <math.h>

// Problem constants
#define BSZ   2
#define TLEN  2048
#define DM    1024
#define DI    2048
#define NST   16
#define DTR   64
#define NPROJ 96
#define MROWS (BSZ*TLEN)    // 4096
#define KSPLIT 8

#define NKC_DM (DM/32)      // 32 k-chunks for K=1024
#define NKC_DI (DI/32)      // 64 k-chunks for K=2048

// Tiles: 128 rows x 32 k bf16 = 8KB, SW64-swizzled 64B rows.
#define TILE_BYTES 8192
#define STAGE_BYTES (4*TILE_BYTES)     // Ah|Al|Bh|Bl = 32KB
#define NSTAGE 3
#define TG_SMEM_BYTES (NSTAGE*STAGE_BYTES)  // 96KB

#define OFF_AL TILE_BYTES
#define OFF_BH (2*TILE_BYTES)
#define OFF_BL (3*TILE_BYTES)

// ---------------------------------------------------------------------------
// Scratch (device globals; zero-initialized — pad rows stay zero)
// ---------------------------------------------------------------------------
__device__ __align__(256) float g_uz[(size_t)MROWS * 2 * DI];
__device__ __align__(256) float g_proj[(size_t)MROWS * NPROJ];
__device__ __align__(256) float g_projp[(size_t)KSPLIT * MROWS * NPROJ];
__device__ __align__(256) float g_delta[(size_t)MROWS * DI];

// pre-tiled, pre-swizzled bf16 operands: 8KB tiles of [128 rows][32 k]
__device__ __align__(256) __nv_bfloat16 gx_h[(size_t)MROWS * DM];      // [32 mt][32 kc]
__device__ __align__(256) __nv_bfloat16 gx_l[(size_t)MROWS * DM];
__device__ __align__(256) __nv_bfloat16 gWinT_h[(size_t)(2*DI) * DM];  // [32 nt][32 kc]
__device__ __align__(256) __nv_bfloat16 gWinT_l[(size_t)(2*DI) * DM];
__device__ __align__(256) __nv_bfloat16 guc_h[(size_t)MROWS * DI];     // [32 mt][64 kc]
__device__ __align__(256) __nv_bfloat16 guc_l[(size_t)MROWS * DI];
__device__ __align__(256) __nv_bfloat16 gWxT_h[(size_t)128 * DI];      // [1 nt][64 kc] rows 96..127 zero
__device__ __align__(256) __nv_bfloat16 gWxT_l[(size_t)128 * DI];
__device__ __align__(256) __nv_bfloat16 gy_h[(size_t)MROWS * DI];      // [32 mt][64 kc]
__device__ __align__(256) __nv_bfloat16 gy_l[(size_t)MROWS * DI];
__device__ __align__(256) __nv_bfloat16 gWoT_h[(size_t)DM * DI];       // [8 nt][64 kc]
__device__ __align__(256) __nv_bfloat16 gWoT_l[(size_t)DM * DI];
// dt GEMM operands
__device__ __align__(256) __nv_bfloat16 gdt_h[(size_t)MROWS * DTR];    // [32 mt][2 kc]
__device__ __align__(256) __nv_bfloat16 gdt_l[(size_t)MROWS * DTR];
__device__ __align__(256) __nv_bfloat16 gWdT_h[(size_t)DI * DTR];      // [16 nt][2 kc]
__device__ __align__(256) __nv_bfloat16 gWdT_l[(size_t)DI * DTR];

// ---------------------------------------------------------------------------
// PTX helpers (sm_90 BASELINE only)
// ---------------------------------------------------------------------------
__device__ __forceinline__ uint32_t smem_u32(const void* p) {
    uint32_t a;
    asm("{ .reg .u64 t; cvta.to.shared.u64 t, %1; cvt.u32.u64 %0, t; }"
        : "=r"(a) : "l"(p));
    return a;
}
__device__ __forceinline__ void bulk_g2s(uint32_t dst, const void* src,
                                         uint32_t bytes, uint32_t mbar) {
    asm volatile(
        "cp.async.bulk.shared::cta.global.mbarrier::complete_tx::bytes "
        "[%0], [%1], %2, [%3];"
        :: "r"(dst), "l"(src), "r"(bytes), "r"(mbar) : "memory");
}
#define MBARRIER_INIT(mb, c) \
    asm volatile("mbarrier.init.shared.b64 [%0], %1;" :: "r"((uint32_t)(mb)), "r"((uint32_t)(c)) : "memory")
#define MBARRIER_INVAL(mb) \
    asm volatile("mbarrier.inval.shared.b64 [%0];" :: "r"((uint32_t)(mb)) : "memory")
#define MBARRIER_EXPECT_TX(mb, tx) \
    asm volatile("mbarrier.arrive.expect_tx.shared.b64 _, [%0], %1;" :: "r"((uint32_t)(mb)), "r"((uint32_t)(tx)) : "memory")

__device__ __forceinline__ void mbar_wait(uint32_t mb, uint32_t parity) {
    uint32_t done;
    asm volatile("{\n\t.reg .pred p;\n\t"
                 "mbarrier.try_wait.parity.acquire.cta.shared::cta.b64 p, [%1], %2;\n\t"
                 "selp.b32 %0, 1, 0, p;\n\t}"
                 : "=r"(done) : "r"(mb), "r"(parity) : "memory");
    if (!done) {
        asm volatile("{\n\t.reg .pred P1;\n\t"
                     "W%=:\n\t"
                     "mbarrier.try_wait.parity.acquire.cta.shared::cta.b64 P1, [%0], %1, 0x989680;\n\t"
                     "@P1 bra.uni D%=;\n\t"
                     "bra.uni W%=;\n\t"
                     "D%=:\n\t}" :: "r"(mb), "r"(parity) : "memory");
    }
}
__device__ __forceinline__ void ldmat_x4(uint32_t* r, uint32_t addr) {
    asm volatile("ldmatrix.sync.aligned.m8n8.x4.shared.b16 {%0,%1,%2,%3}, [%4];"
        : "=r"(r[0]), "=r"(r[1]), "=r"(r[2]), "=r"(r[3]) : "r"(addr));
}
__device__ __forceinline__ void mma16816(float* c, const uint32_t* a, const uint32_t* b) {
    asm volatile(
        "mma.sync.aligned.m16n8k16.row.col.f32.bf16.bf16.f32 "
        "{%0,%1,%2,%3}, {%4,%5,%6,%7}, {%8,%9}, {%0,%1,%2,%3};"
        : "+f"(c[0]), "+f"(c[1]), "+f"(c[2]), "+f"(c[3])
        : "r"(a[0]), "r"(a[1]), "r"(a[2]), "r"(a[3]), "r"(b[0]), "r"(b[1]));
}

// SW64 swizzle inside a 128x32 tile, byte offset
__device__ __forceinline__ uint32_t tile_off(int row, int k) {
    return (uint32_t)(row * 64) + (((uint32_t)(k * 2)) ^ (((uint32_t)(row >> 1) & 3u) << 4));
}
__device__ __forceinline__ float softplusf(float x) {
    return fmaxf(x, 0.f) + log1pf(__expf(-fabsf(x)));
}

// ---------------------------------------------------------------------------
// bf16 3-split HMMA GEMM, bulk-copy pipeline, occ 2.
// EPI=0: plain fp32 store. EPI=1: softplus(acc + bias[col]) store.
// ---------------------------------------------------------------------------
template <int EPI>
__global__ __launch_bounds__(256, 2) void tgemm_bulk(
    const __nv_bfloat16* __restrict__ Ah, const __nv_bfloat16* __restrict__ Al,
    const __nv_bfloat16* __restrict__ Bh, const __nv_bfloat16* __restrict__ Bl,
    float* __restrict__ C, int ldc, int Nvalid, int nkTot, int nkPer, size_t cslice,
    const float* __restrict__ bias)
{
    extern __shared__ char sm[];
    __shared__ uint64_t mbars[NSTAGE];
    const uint32_t smb = smem_u32(sm);
    const uint32_t mb0 = smem_u32(&mbars[0]);

    const int tid = threadIdx.x;
    const int wid = tid >> 5, lane = tid & 31;
    const int wy = wid & 3, wx = wid >> 2;
    const int g = lane >> 2, q2 = (lane & 3) * 2;
    const int mTile = blockIdx.y, nTile = blockIdx.x;
    const int kcB = blockIdx.z * nkPer;
    C += (size_t)blockIdx.z * cslice;

    const int laneA_row = (((lane >> 3) & 1) << 3) + (lane & 7);
    const uint32_t cA = ((lane >> 4) & 1) << 4;
    const uint32_t xorA = (((uint32_t)(laneA_row >> 1)) & 3u) << 4;
    const int laneB_row = (((lane >> 4) & 1) << 3) + (lane & 7);
    const uint32_t cB = ((lane >> 3) & 1) << 4;
    const uint32_t xorB = (((uint32_t)(laneB_row >> 1)) & 3u) << 4;
    const uint32_t aRow = (uint32_t)(wy * 32 + laneA_row) * 64;
    const uint32_t bRow = (uint32_t)(wx * 64 + laneB_row) * 64;

    if (tid == 0) {
#pragma unroll
        for (int s = 0; s < NSTAGE; ++s) MBARRIER_INIT(mb0 + 8 * s, 1);
    }
    __syncthreads();

    float acc[2][8][4];
#pragma unroll
    for (int mi = 0; mi < 2; ++mi)
#pragma unroll
        for (int ni = 0; ni < 8; ++ni)
#pragma unroll
            for (int j = 0; j < 4; ++j) acc[mi][ni][j] = 0.f;

    auto issue = [&](int c, int s) {
        const uint32_t sb = smb + (uint32_t)s * STAGE_BYTES;
        const uint32_t mb = mb0 + 8 * s;
        const size_t kc = (size_t)(kcB + c);
        const size_t aOff = ((size_t)mTile * nkTot + kc) * (TILE_BYTES / 2);
        const size_t bOff = ((size_t)nTile * nkTot + kc) * (TILE_BYTES / 2);
        MBARRIER_EXPECT_TX(mb, STAGE_BYTES);
        bulk_g2s(sb,          Ah + aOff, TILE_BYTES, mb);
        bulk_g2s(sb + OFF_AL, Al + aOff, TILE_BYTES, mb);
        bulk_g2s(sb + OFF_BH, Bh + bOff, TILE_BYTES, mb);
        bulk_g2s(sb + OFF_BL, Bl + bOff, TILE_BYTES, mb);
    };

    if (tid == 0) {
        issue(0, 0);
        if (nkPer > 1) issue(1, 1);
    }

    for (int c = 0; c < nkPer; ++c) {
        const int st = c % NSTAGE;
        if (tid == 0 && c + 2 < nkPer) issue(c + 2, (c + 2) % NSTAGE);
        mbar_wait(mb0 + 8 * st, (uint32_t)((c / NSTAGE) & 1));

        const uint32_t sb = smb + (uint32_t)st * STAGE_BYTES;
#pragma unroll
        for (int kk = 0; kk < 2; ++kk) {
            const uint32_t colA = ((uint32_t)(kk * 32) + cA) ^ xorA;
            const uint32_t colB = ((uint32_t)(kk * 32) + cB) ^ xorB;
            uint32_t ah[2][4], al[2][4];
#pragma unroll
            for (int mi = 0; mi < 2; ++mi) {
                const uint32_t mo = (uint32_t)(mi * 16 * 64);
                ldmat_x4(ah[mi], sb + aRow + mo + colA);
                ldmat_x4(al[mi], sb + OFF_AL + aRow + mo + colA);
            }
#pragma unroll
            for (int nip = 0; nip < 4; ++nip) {
                const uint32_t no = (uint32_t)(nip * 16 * 64);
                uint32_t bh[4], bl[4];
                ldmat_x4(bh, sb + OFF_BH + bRow + no + colB);
                ldmat_x4(bl, sb + OFF_BL + bRow + no + colB);
#pragma unroll
                for (int mi = 0; mi < 2; ++mi) {
                    mma16816(acc[mi][2 * nip],     ah[mi], bh);
                    mma16816(acc[mi][2 * nip],     al[mi], bh);
                    mma16816(acc[mi][2 * nip],     ah[mi], bl);
                    mma16816(acc[mi][2 * nip + 1], ah[mi], bh + 2);
                    mma16816(acc[mi][2 * nip + 1], al[mi], bh + 2);
                    mma16816(acc[mi][2 * nip + 1], ah[mi], bl + 2);
                }
            }
        }
        __syncthreads();
    }

    // epilogue
#pragma unroll
    for (int mi = 0; mi < 2; ++mi) {
        const int row = mTile * 128 + wy * 32 + mi * 16 + g;
#pragma unroll
        for (int ni = 0; ni < 8; ++ni) {
            const int col = nTile * 128 + wx * 64 + ni * 8 + q2;
            if (col < Nvalid) {
                float v0 = acc[mi][ni][0], v1 = acc[mi][ni][1];
                float v2 = acc[mi][ni][2], v3 = acc[mi][ni][3];
                if (EPI == 1) {
                    const float b0 = bias[col], b1 = bias[col + 1];
                    v0 = softplusf(v0 + b0); v1 = softplusf(v1 + b1);
                    v2 = softplusf(v2 + b0); v3 = softplusf(v3 + b1);
                }
                *(float2*)&C[(size_t)row * ldc + col] = make_float2(v0, v1);
                *(float2*)&C[(size_t)(row + 8) * ldc + col] = make_float2(v2, v3);
            }
        }
    }
    __syncthreads();
    if (tid == 0) {
#pragma unroll
        for (int s = 0; s < NSTAGE; ++s) MBARRIER_INVAL(mb0 + 8 * s);
    }
}

// ---------------------------------------------------------------------------
// reduce split-K partials; also emit bf16 hi/lo tiles of the dt columns
// ---------------------------------------------------------------------------
__global__ void reduce_proj_kernel() {
    const size_t i = (size_t)blockIdx.x * blockDim.x + threadIdx.x;
    if (i >= (size_t)MROWS * NPROJ) return;
    float s = 0.f;
#pragma unroll
    for (int z = 0; z < KSPLIT; ++z)
        s += g_projp[(size_t)z * MROWS * NPROJ + i];
    g_proj[i] = s;
    const int m = (int)(i / NPROJ), c = (int)(i % NPROJ);
    if (c < DTR) {
        const __nv_bfloat16 h = __float2bfloat16(s);
        const __nv_bfloat16 l = __float2bfloat16(s - __bfloat162float(h));
        const size_t tile = (size_t)(m >> 7) * 2 + (c >> 5);
        const uint32_t off = tile_off(m & 127, c & 31);
        *(__nv_bfloat16*)((char*)gdt_h + tile * TILE_BYTES + off) = h;
        *(__nv_bfloat16*)((char*)gdt_l + tile * TILE_BYTES + off) = l;
    }
}

// ---------------------------------------------------------------------------
// x -> tiled/swizzled bf16 hi/lo, float4 path (4 k per thread)
// ---------------------------------------------------------------------------
__global__ void split_x_kernel(const float* __restrict__ x)
{
    const size_t i4 = (size_t)blockIdx.x * blockDim.x + threadIdx.x;
    if (i4 >= (size_t)MROWS * DM / 4) return;
    const size_t idx = i4 * 4;
    const int m = (int)(idx / DM), k = (int)(idx % DM);
    const float4 v = *(const float4*)(x + idx);
    __nv_bfloat16 h[4], l[4];
    const float vv[4] = {v.x, v.y, v.z, v.w};
#pragma unroll
    for (int j = 0; j < 4; ++j) {
        h[j] = __float2bfloat16(vv[j]);
        l[j] = __float2bfloat16(vv[j] - __bfloat162float(h[j]));
    }
    const size_t tile = (size_t)(m >> 7) * NKC_DM + (k >> 5);
    const uint32_t off = tile_off(m & 127, k & 31);
    *(uint2*)((char*)gx_h + tile * TILE_BYTES + off) = *(uint2*)h;
    *(uint2*)((char*)gx_l + tile * TILE_BYTES + off) = *(uint2*)l;
}

// ---------------------------------------------------------------------------
// weight transpose+split: src [K][N] fp32 -> [nt][nkTot][128][32]
// ---------------------------------------------------------------------------
__global__ __launch_bounds__(1024) void tsplit_kernel(
    const float* __restrict__ src, __nv_bfloat16* __restrict__ hi,
    __nv_bfloat16* __restrict__ lo, int K, int N, int nkTot)
{
    __shared__ float tile[32][33];
    const int n0 = blockIdx.x * 32, k0 = blockIdx.y * 32;
    const int tx = threadIdx.x & 31, ty = threadIdx.x >> 5;
    tile[ty][tx] = src[(size_t)(k0 + ty) * N + n0 + tx];
    __syncthreads();
    const int k = k0 + tx, n = n0 + ty;
    const float v = tile[tx][ty];
    const __nv_bfloat16 h = __float2bfloat16(v);
    const __nv_bfloat16 l = __float2bfloat16(v - __bfloat162float(h));
    const size_t t = (size_t)(n >> 7) * nkTot + (k >> 5);
    const uint32_t off = tile_off(n & 127, k & 31);
    *(__nv_bfloat16*)((char*)hi + t * TILE_BYTES + off) = h;
    *(__nv_bfloat16*)((char*)lo + t * TILE_BYTES + off) = l;
}

// ---------------------------------------------------------------------------
// Causal conv1d (k=4) + SiLU, t-blocked: each thread computes 4 t x 4 d.
// Reads 7 input rows instead of 16; writes ONLY bf16 hi/lo tiles (no fp32 uc).
// ---------------------------------------------------------------------------
#define NDG (DI/4)    // 512 d-groups
__global__ void conv_silu_kernel(const float* __restrict__ cw,
                                 const float* __restrict__ cb)
{
    const size_t i = (size_t)blockIdx.x * blockDim.x + threadIdx.x;
    if (i >= (size_t)(MROWS / 4) * NDG) return;
    const int dg = (int)(i % NDG), tg = (int)(i / NDG);
    const int d = dg * 4;
    const int m0 = tg * 4;          // global row base (4 consecutive t, same b)
    const int t0 = m0 % TLEN;       // in-batch time of first output

    const float4 b4 = *(const float4*)(cb + d);
    float4 w[4];
#pragma unroll
    for (int j = 0; j < 4; ++j) w[j] = *(const float4*)(cw + (d + j) * 4);

    // input rows t0-3 .. t0+3  (7 rows)
    float4 u[7];
#pragma unroll
    for (int r = 0; r < 7; ++r) {
        const int tt = t0 - 3 + r;
        if (tt >= 0)
            u[r] = *(const float4*)(g_uz + (size_t)(m0 - 3 + r) * (2 * DI) + d);
        else
            u[r] = make_float4(0.f, 0.f, 0.f, 0.f);
    }

    const size_t tileB = ((size_t)(m0 >> 7) * NKC_DI + (d >> 5)) * TILE_BYTES;
#pragma unroll
    for (int lt = 0; lt < 4; ++lt) {
        float a[4] = { b4.x, b4.y, b4.z, b4.w };
#pragma unroll
        for (int k = 0; k < 4; ++k) {
            const float* ur = (const float*)&u[lt + k];
#pragma unroll
            for (int j = 0; j < 4; ++j)
                a[j] += ur[j] * ((const float*)&w[j])[k];
        }
        __nv_bfloat16 h[4], l[4];
#pragma unroll
        for (int j = 0; j < 4; ++j) {
            const float v = a[j] / (1.f + __expf(-a[j]));
            h[j] = __float2bfloat16(v);
            l[j] = __float2bfloat16(v - __bfloat162float(h[j]));
        }
        const uint32_t off = tile_off((m0 + lt) & 127, d & 31);
        *(uint2*)((char*)guc_h + tileB + off) = *(uint2*)h;
        *(uint2*)((char*)guc_l + tileB + off) = *(uint2*)l;
    }
}

// ---------------------------------------------------------------------------
// delta comes from the fused-softplus dt GEMM (tgemm_bulk<1>).
// ---------------------------------------------------------------------------

// ---------------------------------------------------------------------------
// SSM scan (R8-proven layout): 8 lanes per d (2 states each), 256 threads,
// warp = 4 d x 8 n-lanes, smem-tiled 64-step chunks.
// uc is reconstructed from the bf16 hi/lo tiles (hi+lo, err ~2^-17).
// ---------------------------------------------------------------------------
#define SCAN_TB 64
__global__ __launch_bounds__(256) void scan_kernel(
    const float* __restrict__ A_log, const float* __restrict__ Dp)
{
    const int b = blockIdx.y;
    const int tid = threadIdx.x;
    const int warp = tid >> 5;
    const int lane = tid & 31;
    const int d_sub = lane >> 3;
    const int n = lane & 7;
    const int d_local = warp * 4 + d_sub;
    const int d0 = blockIdx.x * 32;
    const int d = d0 + d_local;

    __shared__ float sDelta[SCAN_TB][33];
    __shared__ float sUc[SCAN_TB][33];
    __shared__ float sZ[SCAN_TB][33];
    __shared__ float sY[SCAN_TB][33];
    __shared__ float sB[SCAN_TB][NST];
    __shared__ float sC[SCAN_TB][NST];
    __shared__ float sD[32];

    if (tid < 32) sD[tid] = Dp[d0 + tid];

    const float A0 = -__expf(A_log[(size_t)d * NST + n]);
    const float A1 = -__expf(A_log[(size_t)d * NST + n + 8]);

    float h0 = 0.f, h1 = 0.f;

    for (int t0 = 0; t0 < TLEN; t0 += SCAN_TB) {
        __syncthreads();
        // uc tile base for this 64-row chunk (constant: chunk stays in one
        // 128-row block since t0 is a multiple of 64 and b*TLEN is a multiple
        // of 128)
        const size_t ucBase =
            ((size_t)((b * TLEN + t0) >> 7) * NKC_DI + (d0 >> 5)) * TILE_BYTES;
#pragma unroll
        for (int p = 0; p < 8; ++p) {
            const int i = tid + p * 256;
            const int r = i >> 5, c = i & 31;
            const size_t row = (size_t)(b * TLEN + t0 + r);
            sDelta[r][c] = g_delta[row * DI + d0 + c];
            const uint32_t uoff = tile_off((int)(row & 127), c);
            const float uh = __bfloat162float(
                *(const __nv_bfloat16*)((const char*)guc_h + ucBase + uoff));
            const float ul = __bfloat162float(
                *(const __nv_bfloat16*)((const char*)guc_l + ucBase + uoff));
            sUc[r][c] = uh + ul;
            sZ[r][c] = g_uz[row * (2 * DI) + DI + d0 + c];
            const float v = g_proj[row * NPROJ + DTR + c];
            if (c < NST) sB[r][c] = v;
            else         sC[r][c - NST] = v;
        }
        __syncthreads();

#pragma unroll 4
        for (int tt = 0; tt < SCAN_TB; ++tt) {
            const float delta = sDelta[tt][d_local];
            const float du = delta * sUc[tt][d_local];
            h0 = __expf(delta * A0) * h0 + du * sB[tt][n];
            h1 = __expf(delta * A1) * h1 + du * sB[tt][n + 8];
            float y = h0 * sC[tt][n] + h1 * sC[tt][n + 8];
            y += __shfl_xor_sync(0xffffffffu, y, 1);
            y += __shfl_xor_sync(0xffffffffu, y, 2);
            y += __shfl_xor_sync(0xffffffffu, y, 4);
            if (n == 0) sY[tt][d_local] = y;
        }
        __syncthreads();

#pragma unroll
        for (int p = 0; p < 8; ++p) {
            const int i = tid + p * 256;
            const int r = i >> 5, c = i & 31;
            const float uc = sUc[r][c];
            const float z = sZ[r][c];
            const float gate = z / (1.f + __expf(-z));
            const float v = (sY[r][c] + uc * sD[c]) * gate;
            const int m = b * TLEN + t0 + r;
            const int dd = d0 + c;
            const __nv_bfloat16 h = __float2bfloat16(v);
            const __nv_bfloat16 l = __float2bfloat16(v - __bfloat162float(h));
            const size_t tile = (size_t)(m >> 7) * NKC_DI + (dd >> 5);
            const uint32_t off = tile_off(m & 127, dd & 31);
            *(__nv_bfloat16*)((char*)gy_h + tile * TILE_BYTES + off) = h;
            *(__nv_bfloat16*)((char*)gy_l + tile * TILE_BYTES + off) = l;
        }
    }
}

// ---------------------------------------------------------------------------
extern "C" void kernel_launch(void* const* d_in, const int* in_sizes, int n_in,
                              void* d_out, int out_size)
{
    const float* x      = (const float*)d_in[0];
    const float* W_in   = (const float*)d_in[1];
    const float* conv_w = (const float*)d_in[2];
    const float* conv_b = (const float*)d_in[3];
    const float* W_xprj = (const float*)d_in[4];
    const float* W_dt   = (const float*)d_in[5];
    const float* b_dt   = (const float*)d_in[6];
    const float* A_log  = (const float*)d_in[7];
    const float* Dp     = (const float*)d_in[8];
    const float* W_out  = (const float*)d_in[9];
    float* out = (float*)d_out;

    cudaFuncSetAttribute(tgemm_bulk<0>, cudaFuncAttributeMaxDynamicSharedMemorySize, TG_SMEM_BYTES);
    cudaFuncSetAttribute(tgemm_bulk<1>, cudaFuncAttributeMaxDynamicSharedMemorySize, TG_SMEM_BYTES);

    void *p_uz, *p_projp, *p_delta;
    void *p_xh, *p_xl, *p_WinTh, *p_WinTl, *p_uch, *p_ucl;
    void *p_WxTh, *p_WxTl, *p_yh, *p_yl, *p_WoTh, *p_WoTl;
    void *p_dth, *p_dtl, *p_WdTh, *p_WdTl;
    cudaGetSymbolAddress(&p_uz, g_uz);
    cudaGetSymbolAddress(&p_projp, g_projp);
    cudaGetSymbolAddress(&p_delta, g_delta);
    cudaGetSymbolAddress(&p_xh, gx_h);       cudaGetSymbolAddress(&p_xl, gx_l);
    cudaGetSymbolAddress(&p_WinTh, gWinT_h); cudaGetSymbolAddress(&p_WinTl, gWinT_l);
    cudaGetSymbolAddress(&p_uch, guc_h);     cudaGetSymbolAddress(&p_ucl, guc_l);
    cudaGetSymbolAddress(&p_WxTh, gWxT_h);   cudaGetSymbolAddress(&p_WxTl, gWxT_l);
    cudaGetSymbolAddress(&p_yh, gy_h);       cudaGetSymbolAddress(&p_yl, gy_l);
    cudaGetSymbolAddress(&p_WoTh, gWoT_h);   cudaGetSymbolAddress(&p_WoTl, gWoT_l);
    cudaGetSymbolAddress(&p_dth, gdt_h);     cudaGetSymbolAddress(&p_dtl, gdt_l);
    cudaGetSymbolAddress(&p_WdTh, gWdT_h);   cudaGetSymbolAddress(&p_WdTl, gWdT_l);

    // operand prep (tiled + SW64-swizzled)
    {
        size_t n4 = (size_t)MROWS * DM / 4;
        split_x_kernel<<<(unsigned)((n4 + 255) / 256), 256>>>(x);
    }
    tsplit_kernel<<<dim3((2 * DI) / 32, DM / 32), 1024>>>(
        W_in, (__nv_bfloat16*)p_WinTh, (__nv_bfloat16*)p_WinTl, DM, 2 * DI, NKC_DM);
    tsplit_kernel<<<dim3(NPROJ / 32, DI / 32), 1024>>>(
        W_xprj, (__nv_bfloat16*)p_WxTh, (__nv_bfloat16*)p_WxTl, DI, NPROJ, NKC_DI);
    tsplit_kernel<<<dim3(DM / 32, DI / 32), 1024>>>(
        W_out, (__nv_bfloat16*)p_WoTh, (__nv_bfloat16*)p_WoTl, DI, DM, NKC_DI);
    tsplit_kernel<<<dim3(DI / 32, DTR / 32), 1024>>>(
        W_dt, (__nv_bfloat16*)p_WdTh, (__nv_bfloat16*)p_WdTl, DTR, DI, 2);

    // 1) xz = x @ W_in
    tgemm_bulk<0><<<dim3(32, 32, 1), 256, TG_SMEM_BYTES>>>(
        (const __nv_bfloat16*)p_xh, (const __nv_bfloat16*)p_xl,
        (const __nv_bfloat16*)p_WinTh, (const __nv_bfloat16*)p_WinTl,
        (float*)p_uz, 2 * DI, 2 * DI, NKC_DM, NKC_DM, 0, nullptr);

    // 2) conv + SiLU (t-blocked, bf16 tile output only)
    {
        const size_t total = (size_t)(MROWS / 4) * NDG;
        conv_silu_kernel<<<(unsigned)((total + 255) / 256), 256>>>(conv_w, conv_b);
    }

    // 3) proj = uc @ W_xproj : split-K=8
    tgemm_bulk<0><<<dim3(1, 32, KSPLIT), 256, TG_SMEM_BYTES>>>(
        (const __nv_bfloat16*)p_uch, (const __nv_bfloat16*)p_ucl,
        (const __nv_bfloat16*)p_WxTh, (const __nv_bfloat16*)p_WxTl,
        (float*)p_projp, NPROJ, NPROJ, NKC_DI, NKC_DI / KSPLIT,
        (size_t)MROWS * NPROJ, nullptr);
    {
        const size_t total = (size_t)MROWS * NPROJ;
        reduce_proj_kernel<<<(unsigned)((total + 255) / 256), 256>>>();
    }

    // 4) delta = softplus(proj_dt @ W_dt + b_dt)  (tensor GEMM, fused epi)
    tgemm_bulk<1><<<dim3(DI / 128, 32, 1), 256, TG_SMEM_BYTES>>>(
        (const __nv_bfloat16*)p_dth, (const __nv_bfloat16*)p_dtl,
        (const __nv_bfloat16*)p_WdTh, (const __nv_bfloat16*)p_WdTl,
        (float*)p_delta, DI, DI, 2, 2, 0, b_dt);

    // 5) scan
    scan_kernel<<<dim3(DI / 32, BSZ), 256>>>(A_log, Dp);

    // 6) out = y @ W_out
    tgemm_bulk<0><<<dim3(8, 32, 1), 256, TG_SMEM_BYTES>>>(
        (const __nv_bfloat16*)p_yh, (const __nv_bfloat16*)p_yl,
        (const __nv_bfloat16*)p_WoTh, (const __nv_bfloat16*)p_WoTl,
        out, DM, DM, NKC_DI, NKC_DI, 0, nullptr);
}

// round 13
// speedup vs baseline: 1.1004x; 1.1004x over previous
#include <cuda_runtime.h>
#include <cuda_bf16.h>
#include <cstdint>
#include <math.h>

// Problem constants
#define BSZ   2
#define TLEN  2048
#define DM    1024
#define DI    2048
#define NST   16
#define DTR   64
#define NPROJ 96
#define MROWS (BSZ*TLEN)    // 4096
#define KSPLIT 8

#define NKC_DM (DM/32)      // 32 k-chunks for K=1024
#define NKC_DI (DI/32)      // 64 k-chunks for K=2048

// Tiles: 128 rows x 32 k bf16 = 8KB, SW64-swizzled 64B rows.
#define TILE_BYTES 8192
#define STAGE_BYTES (4*TILE_BYTES)     // Ah|Al|Bh|Bl = 32KB
#define NSTAGE 3
#define TG_SMEM_BYTES (NSTAGE*STAGE_BYTES)  // 96KB

#define OFF_AL TILE_BYTES
#define OFF_BH (2*TILE_BYTES)
#define OFF_BL (3*TILE_BYTES)

// ---------------------------------------------------------------------------
// Scratch (device globals; zero-initialized — pad rows stay zero)
// ---------------------------------------------------------------------------
__device__ __align__(256) float g_uz[(size_t)MROWS * 2 * DI];
__device__ __align__(256) float g_uc[(size_t)MROWS * DI];
__device__ __align__(256) float g_proj[(size_t)MROWS * NPROJ];
__device__ __align__(256) float g_projp[(size_t)KSPLIT * MROWS * NPROJ];
__device__ __align__(256) float g_delta[(size_t)MROWS * DI];

// pre-tiled, pre-swizzled bf16 operands: 8KB tiles of [128 rows][32 k]
__device__ __align__(256) __nv_bfloat16 gx_h[(size_t)MROWS * DM];      // [32 mt][32 kc]
__device__ __align__(256) __nv_bfloat16 gx_l[(size_t)MROWS * DM];
__device__ __align__(256) __nv_bfloat16 gWinT_h[(size_t)(2*DI) * DM];  // [32 nt][32 kc]
__device__ __align__(256) __nv_bfloat16 gWinT_l[(size_t)(2*DI) * DM];
__device__ __align__(256) __nv_bfloat16 guc_h[(size_t)MROWS * DI];     // [32 mt][64 kc]
__device__ __align__(256) __nv_bfloat16 guc_l[(size_t)MROWS * DI];
__device__ __align__(256) __nv_bfloat16 gWxT_h[(size_t)128 * DI];      // [1 nt][64 kc] rows 96..127 zero
__device__ __align__(256) __nv_bfloat16 gWxT_l[(size_t)128 * DI];
__device__ __align__(256) __nv_bfloat16 gy_h[(size_t)MROWS * DI];      // [32 mt][64 kc]
__device__ __align__(256) __nv_bfloat16 gy_l[(size_t)MROWS * DI];
__device__ __align__(256) __nv_bfloat16 gWoT_h[(size_t)DM * DI];       // [8 nt][64 kc]
__device__ __align__(256) __nv_bfloat16 gWoT_l[(size_t)DM * DI];
// dt GEMM operands
__device__ __align__(256) __nv_bfloat16 gdt_h[(size_t)MROWS * DTR];    // [32 mt][2 kc]
__device__ __align__(256) __nv_bfloat16 gdt_l[(size_t)MROWS * DTR];
__device__ __align__(256) __nv_bfloat16 gWdT_h[(size_t)DI * DTR];      // [16 nt][2 kc]
__device__ __align__(256) __nv_bfloat16 gWdT_l[(size_t)DI * DTR];

// ---------------------------------------------------------------------------
// PTX helpers (sm_90 BASELINE only)
// ---------------------------------------------------------------------------
__device__ __forceinline__ uint32_t smem_u32(const void* p) {
    uint32_t a;
    asm("{ .reg .u64 t; cvta.to.shared.u64 t, %1; cvt.u32.u64 %0, t; }"
        : "=r"(a) : "l"(p));
    return a;
}
__device__ __forceinline__ void bulk_g2s(uint32_t dst, const void* src,
                                         uint32_t bytes, uint32_t mbar) {
    asm volatile(
        "cp.async.bulk.shared::cta.global.mbarrier::complete_tx::bytes "
        "[%0], [%1], %2, [%3];"
        :: "r"(dst), "l"(src), "r"(bytes), "r"(mbar) : "memory");
}
#define MBARRIER_INIT(mb, c) \
    asm volatile("mbarrier.init.shared.b64 [%0], %1;" :: "r"((uint32_t)(mb)), "r"((uint32_t)(c)) : "memory")
#define MBARRIER_INVAL(mb) \
    asm volatile("mbarrier.inval.shared.b64 [%0];" :: "r"((uint32_t)(mb)) : "memory")
#define MBARRIER_EXPECT_TX(mb, tx) \
    asm volatile("mbarrier.arrive.expect_tx.shared.b64 _, [%0], %1;" :: "r"((uint32_t)(mb)), "r"((uint32_t)(tx)) : "memory")

__device__ __forceinline__ void mbar_wait(uint32_t mb, uint32_t parity) {
    uint32_t done;
    asm volatile("{\n\t.reg .pred p;\n\t"
                 "mbarrier.try_wait.parity.acquire.cta.shared::cta.b64 p, [%1], %2;\n\t"
                 "selp.b32 %0, 1, 0, p;\n\t}"
                 : "=r"(done) : "r"(mb), "r"(parity) : "memory");
    if (!done) {
        asm volatile("{\n\t.reg .pred P1;\n\t"
                     "W%=:\n\t"
                     "mbarrier.try_wait.parity.acquire.cta.shared::cta.b64 P1, [%0], %1, 0x989680;\n\t"
                     "@P1 bra.uni D%=;\n\t"
                     "bra.uni W%=;\n\t"
                     "D%=:\n\t}" :: "r"(mb), "r"(parity) : "memory");
    }
}
__device__ __forceinline__ void ldmat_x4(uint32_t* r, uint32_t addr) {
    asm volatile("ldmatrix.sync.aligned.m8n8.x4.shared.b16 {%0,%1,%2,%3}, [%4];"
        : "=r"(r[0]), "=r"(r[1]), "=r"(r[2]), "=r"(r[3]) : "r"(addr));
}
__device__ __forceinline__ void mma16816(float* c, const uint32_t* a, const uint32_t* b) {
    asm volatile(
        "mma.sync.aligned.m16n8k16.row.col.f32.bf16.bf16.f32 "
        "{%0,%1,%2,%3}, {%4,%5,%6,%7}, {%8,%9}, {%0,%1,%2,%3};"
        : "+f"(c[0]), "+f"(c[1]), "+f"(c[2]), "+f"(c[3])
        : "r"(a[0]), "r"(a[1]), "r"(a[2]), "r"(a[3]), "r"(b[0]), "r"(b[1]));
}

// SW64 swizzle inside a 128x32 tile, byte offset
__device__ __forceinline__ uint32_t tile_off(int row, int k) {
    return (uint32_t)(row * 64) + (((uint32_t)(k * 2)) ^ (((uint32_t)(row >> 1) & 3u) << 4));
}
__device__ __forceinline__ float softplusf(float x) {
    return fmaxf(x, 0.f) + log1pf(__expf(-fabsf(x)));
}

// ---------------------------------------------------------------------------
// bf16 3-split HMMA GEMM, bulk-copy pipeline, occ 2.
// EPI=0: plain fp32 store. EPI=1: softplus(acc + bias[col]) store.
// ---------------------------------------------------------------------------
template <int EPI>
__global__ __launch_bounds__(256, 2) void tgemm_bulk(
    const __nv_bfloat16* __restrict__ Ah, const __nv_bfloat16* __restrict__ Al,
    const __nv_bfloat16* __restrict__ Bh, const __nv_bfloat16* __restrict__ Bl,
    float* __restrict__ C, int ldc, int Nvalid, int nkTot, int nkPer, size_t cslice,
    const float* __restrict__ bias)
{
    extern __shared__ char sm[];
    __shared__ uint64_t mbars[NSTAGE];
    const uint32_t smb = smem_u32(sm);
    const uint32_t mb0 = smem_u32(&mbars[0]);

    const int tid = threadIdx.x;
    const int wid = tid >> 5, lane = tid & 31;
    const int wy = wid & 3, wx = wid >> 2;
    const int g = lane >> 2, q2 = (lane & 3) * 2;
    const int mTile = blockIdx.y, nTile = blockIdx.x;
    const int kcB = blockIdx.z * nkPer;
    C += (size_t)blockIdx.z * cslice;

    const int laneA_row = (((lane >> 3) & 1) << 3) + (lane & 7);
    const uint32_t cA = ((lane >> 4) & 1) << 4;
    const uint32_t xorA = (((uint32_t)(laneA_row >> 1)) & 3u) << 4;
    const int laneB_row = (((lane >> 4) & 1) << 3) + (lane & 7);
    const uint32_t cB = ((lane >> 3) & 1) << 4;
    const uint32_t xorB = (((uint32_t)(laneB_row >> 1)) & 3u) << 4;
    const uint32_t aRow = (uint32_t)(wy * 32 + laneA_row) * 64;
    const uint32_t bRow = (uint32_t)(wx * 64 + laneB_row) * 64;

    if (tid == 0) {
#pragma unroll
        for (int s = 0; s < NSTAGE; ++s) MBARRIER_INIT(mb0 + 8 * s, 1);
    }
    __syncthreads();

    float acc[2][8][4];
#pragma unroll
    for (int mi = 0; mi < 2; ++mi)
#pragma unroll
        for (int ni = 0; ni < 8; ++ni)
#pragma unroll
            for (int j = 0; j < 4; ++j) acc[mi][ni][j] = 0.f;

    auto issue = [&](int c, int s) {
        const uint32_t sb = smb + (uint32_t)s * STAGE_BYTES;
        const uint32_t mb = mb0 + 8 * s;
        const size_t kc = (size_t)(kcB + c);
        const size_t aOff = ((size_t)mTile * nkTot + kc) * (TILE_BYTES / 2);
        const size_t bOff = ((size_t)nTile * nkTot + kc) * (TILE_BYTES / 2);
        MBARRIER_EXPECT_TX(mb, STAGE_BYTES);
        bulk_g2s(sb,          Ah + aOff, TILE_BYTES, mb);
        bulk_g2s(sb + OFF_AL, Al + aOff, TILE_BYTES, mb);
        bulk_g2s(sb + OFF_BH, Bh + bOff, TILE_BYTES, mb);
        bulk_g2s(sb + OFF_BL, Bl + bOff, TILE_BYTES, mb);
    };

    if (tid == 0) {
        issue(0, 0);
        if (nkPer > 1) issue(1, 1);
    }

    for (int c = 0; c < nkPer; ++c) {
        const int st = c % NSTAGE;
        if (tid == 0 && c + 2 < nkPer) issue(c + 2, (c + 2) % NSTAGE);
        mbar_wait(mb0 + 8 * st, (uint32_t)((c / NSTAGE) & 1));

        const uint32_t sb = smb + (uint32_t)st * STAGE_BYTES;
#pragma unroll
        for (int kk = 0; kk < 2; ++kk) {
            const uint32_t colA = ((uint32_t)(kk * 32) + cA) ^ xorA;
            const uint32_t colB = ((uint32_t)(kk * 32) + cB) ^ xorB;
            uint32_t ah[2][4], al[2][4];
#pragma unroll
            for (int mi = 0; mi < 2; ++mi) {
                const uint32_t mo = (uint32_t)(mi * 16 * 64);
                ldmat_x4(ah[mi], sb + aRow + mo + colA);
                ldmat_x4(al[mi], sb + OFF_AL + aRow + mo + colA);
            }
#pragma unroll
            for (int nip = 0; nip < 4; ++nip) {
                const uint32_t no = (uint32_t)(nip * 16 * 64);
                uint32_t bh[4], bl[4];
                ldmat_x4(bh, sb + OFF_BH + bRow + no + colB);
                ldmat_x4(bl, sb + OFF_BL + bRow + no + colB);
#pragma unroll
                for (int mi = 0; mi < 2; ++mi) {
                    mma16816(acc[mi][2 * nip],     ah[mi], bh);
                    mma16816(acc[mi][2 * nip],     al[mi], bh);
                    mma16816(acc[mi][2 * nip],     ah[mi], bl);
                    mma16816(acc[mi][2 * nip + 1], ah[mi], bh + 2);
                    mma16816(acc[mi][2 * nip + 1], al[mi], bh + 2);
                    mma16816(acc[mi][2 * nip + 1], ah[mi], bl + 2);
                }
            }
        }
        __syncthreads();
    }

    // epilogue
#pragma unroll
    for (int mi = 0; mi < 2; ++mi) {
        const int row = mTile * 128 + wy * 32 + mi * 16 + g;
#pragma unroll
        for (int ni = 0; ni < 8; ++ni) {
            const int col = nTile * 128 + wx * 64 + ni * 8 + q2;
            if (col < Nvalid) {
                float v0 = acc[mi][ni][0], v1 = acc[mi][ni][1];
                float v2 = acc[mi][ni][2], v3 = acc[mi][ni][3];
                if (EPI == 1) {
                    const float b0 = bias[col], b1 = bias[col + 1];
                    v0 = softplusf(v0 + b0); v1 = softplusf(v1 + b1);
                    v2 = softplusf(v2 + b0); v3 = softplusf(v3 + b1);
                }
                *(float2*)&C[(size_t)row * ldc + col] = make_float2(v0, v1);
                *(float2*)&C[(size_t)(row + 8) * ldc + col] = make_float2(v2, v3);
            }
        }
    }
    __syncthreads();
    if (tid == 0) {
#pragma unroll
        for (int s = 0; s < NSTAGE; ++s) MBARRIER_INVAL(mb0 + 8 * s);
    }
}

// ---------------------------------------------------------------------------
// reduce split-K partials; also emit bf16 hi/lo tiles of the dt columns
// ---------------------------------------------------------------------------
__global__ void reduce_proj_kernel() {
    const size_t i = (size_t)blockIdx.x * blockDim.x + threadIdx.x;
    if (i >= (size_t)MROWS * NPROJ) return;
    float s = 0.f;
#pragma unroll
    for (int z = 0; z < KSPLIT; ++z)
        s += g_projp[(size_t)z * MROWS * NPROJ + i];
    g_proj[i] = s;
    const int m = (int)(i / NPROJ), c = (int)(i % NPROJ);
    if (c < DTR) {
        const __nv_bfloat16 h = __float2bfloat16(s);
        const __nv_bfloat16 l = __float2bfloat16(s - __bfloat162float(h));
        const size_t tile = (size_t)(m >> 7) * 2 + (c >> 5);
        const uint32_t off = tile_off(m & 127, c & 31);
        *(__nv_bfloat16*)((char*)gdt_h + tile * TILE_BYTES + off) = h;
        *(__nv_bfloat16*)((char*)gdt_l + tile * TILE_BYTES + off) = l;
    }
}

// ---------------------------------------------------------------------------
// x -> tiled/swizzled bf16 hi/lo, float4 path (4 k per thread)
// ---------------------------------------------------------------------------
__global__ void split_x_kernel(const float* __restrict__ x)
{
    const size_t i4 = (size_t)blockIdx.x * blockDim.x + threadIdx.x;
    if (i4 >= (size_t)MROWS * DM / 4) return;
    const size_t idx = i4 * 4;
    const int m = (int)(idx / DM), k = (int)(idx % DM);
    const float4 v = *(const float4*)(x + idx);
    __nv_bfloat16 h[4], l[4];
    const float vv[4] = {v.x, v.y, v.z, v.w};
#pragma unroll
    for (int j = 0; j < 4; ++j) {
        h[j] = __float2bfloat16(vv[j]);
        l[j] = __float2bfloat16(vv[j] - __bfloat162float(h[j]));
    }
    const size_t tile = (size_t)(m >> 7) * NKC_DM + (k >> 5);
    const uint32_t off = tile_off(m & 127, k & 31);
    *(uint2*)((char*)gx_h + tile * TILE_BYTES + off) = *(uint2*)h;
    *(uint2*)((char*)gx_l + tile * TILE_BYTES + off) = *(uint2*)l;
}

// ---------------------------------------------------------------------------
// weight transpose+split: src [K][N] fp32 -> [nt][nkTot][128][32]
// ---------------------------------------------------------------------------
__global__ __launch_bounds__(1024) void tsplit_kernel(
    const float* __restrict__ src, __nv_bfloat16* __restrict__ hi,
    __nv_bfloat16* __restrict__ lo, int K, int N, int nkTot)
{
    __shared__ float tile[32][33];
    const int n0 = blockIdx.x * 32, k0 = blockIdx.y * 32;
    const int tx = threadIdx.x & 31, ty = threadIdx.x >> 5;
    tile[ty][tx] = src[(size_t)(k0 + ty) * N + n0 + tx];
    __syncthreads();
    const int k = k0 + tx, n = n0 + ty;
    const float v = tile[tx][ty];
    const __nv_bfloat16 h = __float2bfloat16(v);
    const __nv_bfloat16 l = __float2bfloat16(v - __bfloat162float(h));
    const size_t t = (size_t)(n >> 7) * nkTot + (k >> 5);
    const uint32_t off = tile_off(n & 127, k & 31);
    *(__nv_bfloat16*)((char*)hi + t * TILE_BYTES + off) = h;
    *(__nv_bfloat16*)((char*)lo + t * TILE_BYTES + off) = l;
}

// ---------------------------------------------------------------------------
// Causal conv1d (k=4) + SiLU, t-blocked: each thread computes 4 t x 4 d.
// Reads 7 input rows instead of 16. Writes fp32 uc (for scan) AND bf16 tiles.
// ---------------------------------------------------------------------------
#define NDG (DI/4)    // 512 d-groups
__global__ void conv_silu_kernel(const float* __restrict__ cw,
                                 const float* __restrict__ cb)
{
    const size_t i = (size_t)blockIdx.x * blockDim.x + threadIdx.x;
    if (i >= (size_t)(MROWS / 4) * NDG) return;
    const int dg = (int)(i % NDG), tg = (int)(i / NDG);
    const int d = dg * 4;
    const int m0 = tg * 4;          // global row base (4 consecutive t, same b)
    const int t0 = m0 % TLEN;       // in-batch time of first output

    const float4 b4 = *(const float4*)(cb + d);
    float4 w[4];
#pragma unroll
    for (int j = 0; j < 4; ++j) w[j] = *(const float4*)(cw + (d + j) * 4);

    // input rows t0-3 .. t0+3  (7 rows)
    float4 u[7];
#pragma unroll
    for (int r = 0; r < 7; ++r) {
        const int tt = t0 - 3 + r;
        if (tt >= 0)
            u[r] = *(const float4*)(g_uz + (size_t)(m0 - 3 + r) * (2 * DI) + d);
        else
            u[r] = make_float4(0.f, 0.f, 0.f, 0.f);
    }

    const size_t tileB = ((size_t)(m0 >> 7) * NKC_DI + (d >> 5)) * TILE_BYTES;
#pragma unroll
    for (int lt = 0; lt < 4; ++lt) {
        float a[4] = { b4.x, b4.y, b4.z, b4.w };
#pragma unroll
        for (int k = 0; k < 4; ++k) {
            const float* ur = (const float*)&u[lt + k];
#pragma unroll
            for (int j = 0; j < 4; ++j)
                a[j] += ur[j] * ((const float*)&w[j])[k];
        }
        float v[4];
        __nv_bfloat16 h[4], l[4];
#pragma unroll
        for (int j = 0; j < 4; ++j) {
            v[j] = a[j] / (1.f + __expf(-a[j]));
            h[j] = __float2bfloat16(v[j]);
            l[j] = __float2bfloat16(v[j] - __bfloat162float(h[j]));
        }
        *(float4*)(g_uc + (size_t)(m0 + lt) * DI + d) =
            make_float4(v[0], v[1], v[2], v[3]);
        const uint32_t off = tile_off((m0 + lt) & 127, d & 31);
        *(uint2*)((char*)guc_h + tileB + off) = *(uint2*)h;
        *(uint2*)((char*)guc_l + tileB + off) = *(uint2*)l;
    }
}

// ---------------------------------------------------------------------------
// SSM scan (R8/R10-proven layout): 8 lanes per d (2 states each), 256 threads,
// warp = 4 d x 8 n-lanes, smem-tiled 64-step chunks. Reads fp32 uc (coalesced).
// ---------------------------------------------------------------------------
#define SCAN_TB 64
__global__ __launch_bounds__(256) void scan_kernel(
    const float* __restrict__ A_log, const float* __restrict__ Dp)
{
    const int b = blockIdx.y;
    const int tid = threadIdx.x;
    const int warp = tid >> 5;
    const int lane = tid & 31;
    const int d_sub = lane >> 3;
    const int n = lane & 7;
    const int d_local = warp * 4 + d_sub;
    const int d0 = blockIdx.x * 32;
    const int d = d0 + d_local;

    __shared__ float sDelta[SCAN_TB][33];
    __shared__ float sUc[SCAN_TB][33];
    __shared__ float sZ[SCAN_TB][33];
    __shared__ float sY[SCAN_TB][33];
    __shared__ float sB[SCAN_TB][NST];
    __shared__ float sC[SCAN_TB][NST];
    __shared__ float sD[32];

    if (tid < 32) sD[tid] = Dp[d0 + tid];

    const float A0 = -__expf(A_log[(size_t)d * NST + n]);
    const float A1 = -__expf(A_log[(size_t)d * NST + n + 8]);

    float h0 = 0.f, h1 = 0.f;

    for (int t0 = 0; t0 < TLEN; t0 += SCAN_TB) {
        __syncthreads();
#pragma unroll
        for (int p = 0; p < 8; ++p) {
            const int i = tid + p * 256;
            const int r = i >> 5, c = i & 31;
            const size_t row = (size_t)(b * TLEN + t0 + r);
            sDelta[r][c] = g_delta[row * DI + d0 + c];
            sUc[r][c]    = g_uc[row * DI + d0 + c];
            sZ[r][c]     = g_uz[row * (2 * DI) + DI + d0 + c];
            const float v = g_proj[row * NPROJ + DTR + c];
            if (c < NST) sB[r][c] = v;
            else         sC[r][c - NST] = v;
        }
        __syncthreads();

#pragma unroll 4
        for (int tt = 0; tt < SCAN_TB; ++tt) {
            const float delta = sDelta[tt][d_local];
            const float du = delta * sUc[tt][d_local];
            h0 = __expf(delta * A0) * h0 + du * sB[tt][n];
            h1 = __expf(delta * A1) * h1 + du * sB[tt][n + 8];
            float y = h0 * sC[tt][n] + h1 * sC[tt][n + 8];
            y += __shfl_xor_sync(0xffffffffu, y, 1);
            y += __shfl_xor_sync(0xffffffffu, y, 2);
            y += __shfl_xor_sync(0xffffffffu, y, 4);
            if (n == 0) sY[tt][d_local] = y;
        }
        __syncthreads();

#pragma unroll
        for (int p = 0; p < 8; ++p) {
            const int i = tid + p * 256;
            const int r = i >> 5, c = i & 31;
            const float uc = sUc[r][c];
            const float z = sZ[r][c];
            const float gate = z / (1.f + __expf(-z));
            const float v = (sY[r][c] + uc * sD[c]) * gate;
            const int m = b * TLEN + t0 + r;
            const int dd = d0 + c;
            const __nv_bfloat16 h = __float2bfloat16(v);
            const __nv_bfloat16 l = __float2bfloat16(v - __bfloat162float(h));
            const size_t tile = (size_t)(m >> 7) * NKC_DI + (dd >> 5);
            const uint32_t off = tile_off(m & 127, dd & 31);
            *(__nv_bfloat16*)((char*)gy_h + tile * TILE_BYTES + off) = h;
            *(__nv_bfloat16*)((char*)gy_l + tile * TILE_BYTES + off) = l;
        }
    }
}

// ---------------------------------------------------------------------------
extern "C" void kernel_launch(void* const* d_in, const int* in_sizes, int n_in,
                              void* d_out, int out_size)
{
    const float* x      = (const float*)d_in[0];
    const float* W_in   = (const float*)d_in[1];
    const float* conv_w = (const float*)d_in[2];
    const float* conv_b = (const float*)d_in[3];
    const float* W_xprj = (const float*)d_in[4];
    const float* W_dt   = (const float*)d_in[5];
    const float* b_dt   = (const float*)d_in[6];
    const float* A_log  = (const float*)d_in[7];
    const float* Dp     = (const float*)d_in[8];
    const float* W_out  = (const float*)d_in[9];
    float* out = (float*)d_out;

    cudaFuncSetAttribute(tgemm_bulk<0>, cudaFuncAttributeMaxDynamicSharedMemorySize, TG_SMEM_BYTES);
    cudaFuncSetAttribute(tgemm_bulk<1>, cudaFuncAttributeMaxDynamicSharedMemorySize, TG_SMEM_BYTES);

    void *p_uz, *p_projp, *p_delta;
    void *p_xh, *p_xl, *p_WinTh, *p_WinTl, *p_uch, *p_ucl;
    void *p_WxTh, *p_WxTl, *p_yh, *p_yl, *p_WoTh, *p_WoTl;
    void *p_dth, *p_dtl, *p_WdTh, *p_WdTl;
    cudaGetSymbolAddress(&p_uz, g_uz);
    cudaGetSymbolAddress(&p_projp, g_projp);
    cudaGetSymbolAddress(&p_delta, g_delta);
    cudaGetSymbolAddress(&p_xh, gx_h);       cudaGetSymbolAddress(&p_xl, gx_l);
    cudaGetSymbolAddress(&p_WinTh, gWinT_h); cudaGetSymbolAddress(&p_WinTl, gWinT_l);
    cudaGetSymbolAddress(&p_uch, guc_h);     cudaGetSymbolAddress(&p_ucl, guc_l);
    cudaGetSymbolAddress(&p_WxTh, gWxT_h);   cudaGetSymbolAddress(&p_WxTl, gWxT_l);
    cudaGetSymbolAddress(&p_yh, gy_h);       cudaGetSymbolAddress(&p_yl, gy_l);
    cudaGetSymbolAddress(&p_WoTh, gWoT_h);   cudaGetSymbolAddress(&p_WoTl, gWoT_l);
    cudaGetSymbolAddress(&p_dth, gdt_h);     cudaGetSymbolAddress(&p_dtl, gdt_l);
    cudaGetSymbolAddress(&p_WdTh, gWdT_h);   cudaGetSymbolAddress(&p_WdTl, gWdT_l);

    // operand prep (tiled + SW64-swizzled)
    {
        size_t n4 = (size_t)MROWS * DM / 4;
        split_x_kernel<<<(unsigned)((n4 + 255) / 256), 256>>>(x);
    }
    tsplit_kernel<<<dim3((2 * DI) / 32, DM / 32), 1024>>>(
        W_in, (__nv_bfloat16*)p_WinTh, (__nv_bfloat16*)p_WinTl, DM, 2 * DI, NKC_DM);
    tsplit_kernel<<<dim3(NPROJ / 32, DI / 32), 1024>>>(
        W_xprj, (__nv_bfloat16*)p_WxTh, (__nv_bfloat16*)p_WxTl, DI, NPROJ, NKC_DI);
    tsplit_kernel<<<dim3(DM / 32, DI / 32), 1024>>>(
        W_out, (__nv_bfloat16*)p_WoTh, (__nv_bfloat16*)p_WoTl, DI, DM, NKC_DI);
    tsplit_kernel<<<dim3(DI / 32, DTR / 32), 1024>>>(
        W_dt, (__nv_bfloat16*)p_WdTh, (__nv_bfloat16*)p_WdTl, DTR, DI, 2);

    // 1) xz = x @ W_in
    tgemm_bulk<0><<<dim3(32, 32, 1), 256, TG_SMEM_BYTES>>>(
        (const __nv_bfloat16*)p_xh, (const __nv_bfloat16*)p_xl,
        (const __nv_bfloat16*)p_WinTh, (const __nv_bfloat16*)p_WinTl,
        (float*)p_uz, 2 * DI, 2 * DI, NKC_DM, NKC_DM, 0, nullptr);

    // 2) conv + SiLU (t-blocked; fp32 uc + bf16 tiles)
    {
        const size_t total = (size_t)(MROWS / 4) * NDG;
        conv_silu_kernel<<<(unsigned)((total + 255) / 256), 256>>>(conv_w, conv_b);
    }

    // 3) proj = uc @ W_xproj : split-K=8
    tgemm_bulk<0><<<dim3(1, 32, KSPLIT), 256, TG_SMEM_BYTES>>>(
        (const __nv_bfloat16*)p_uch, (const __nv_bfloat16*)p_ucl,
        (const __nv_bfloat16*)p_WxTh, (const __nv_bfloat16*)p_WxTl,
        (float*)p_projp, NPROJ, NPROJ, NKC_DI, NKC_DI / KSPLIT,
        (size_t)MROWS * NPROJ, nullptr);
    {
        const size_t total = (size_t)MROWS * NPROJ;
        reduce_proj_kernel<<<(unsigned)((total + 255) / 256), 256>>>();
    }

    // 4) delta = softplus(proj_dt @ W_dt + b_dt)  (tensor GEMM, fused epi)
    tgemm_bulk<1><<<dim3(DI / 128, 32, 1), 256, TG_SMEM_BYTES>>>(
        (const __nv_bfloat16*)p_dth, (const __nv_bfloat16*)p_dtl,
        (const __nv_bfloat16*)p_WdTh, (const __nv_bfloat16*)p_WdTl,
        (float*)p_delta, DI, DI, 2, 2, 0, b_dt);

    // 5) scan
    scan_kernel<<<dim3(DI / 32, BSZ), 256>>>(A_log, Dp);

    // 6) out = y @ W_out
    tgemm_bulk<0><<<dim3(8, 32, 1), 256, TG_SMEM_BYTES>>>(
        (const __nv_bfloat16*)p_yh, (const __nv_bfloat16*)p_yl,
        (const __nv_bfloat16*)p_WoTh, (const __nv_bfloat16*)p_WoTl,
        out, DM, DM, NKC_DI, NKC_DI, 0, nullptr);
}

// round 14
// speedup vs baseline: 1.1429x; 1.0386x over previous
#include <cuda_runtime.h>
#include <cuda_bf16.h>
#include <cstdint>
#include <math.h>

// Problem constants
#define BSZ   2
#define TLEN  2048
#define DM    1024
#define DI    2048
#define NST   16
#define DTR   64
#define NPROJ 96
#define MROWS (BSZ*TLEN)    // 4096
#define KSPLIT 8

#define NKC_DM (DM/32)      // 32 k-chunks for K=1024
#define NKC_DI (DI/32)      // 64 k-chunks for K=2048

// Tiles: 128 rows x 32 k bf16 = 8KB, SW64-swizzled 64B rows.
#define TILE_BYTES 8192
#define STAGE_BYTES (4*TILE_BYTES)     // Ah|Al|Bh|Bl = 32KB
#define NSTAGE 3
#define TG_SMEM_BYTES (NSTAGE*STAGE_BYTES)  // 96KB

#define OFF_AL TILE_BYTES
#define OFF_BH (2*TILE_BYTES)
#define OFF_BL (3*TILE_BYTES)

// ---------------------------------------------------------------------------
// Scratch (device globals; zero-initialized — pad rows stay zero)
// ---------------------------------------------------------------------------
__device__ __align__(256) float g_uz[(size_t)MROWS * 2 * DI];
__device__ __align__(256) float g_uc[(size_t)MROWS * DI];
__device__ __align__(256) float g_proj[(size_t)MROWS * NPROJ];
__device__ __align__(256) float g_projp[(size_t)KSPLIT * MROWS * NPROJ];
__device__ __align__(256) float g_delta[(size_t)MROWS * DI];

// pre-tiled, pre-swizzled bf16 operands: 8KB tiles of [128 rows][32 k]
__device__ __align__(256) __nv_bfloat16 gx_h[(size_t)MROWS * DM];
__device__ __align__(256) __nv_bfloat16 gx_l[(size_t)MROWS * DM];
__device__ __align__(256) __nv_bfloat16 gWinT_h[(size_t)(2*DI) * DM];
__device__ __align__(256) __nv_bfloat16 gWinT_l[(size_t)(2*DI) * DM];
__device__ __align__(256) __nv_bfloat16 guc_h[(size_t)MROWS * DI];
__device__ __align__(256) __nv_bfloat16 guc_l[(size_t)MROWS * DI];
__device__ __align__(256) __nv_bfloat16 gWxT_h[(size_t)128 * DI];
__device__ __align__(256) __nv_bfloat16 gWxT_l[(size_t)128 * DI];
__device__ __align__(256) __nv_bfloat16 gy_h[(size_t)MROWS * DI];
__device__ __align__(256) __nv_bfloat16 gy_l[(size_t)MROWS * DI];
__device__ __align__(256) __nv_bfloat16 gWoT_h[(size_t)DM * DI];
__device__ __align__(256) __nv_bfloat16 gWoT_l[(size_t)DM * DI];
// dt GEMM operands
__device__ __align__(256) __nv_bfloat16 gdt_h[(size_t)MROWS * DTR];
__device__ __align__(256) __nv_bfloat16 gdt_l[(size_t)MROWS * DTR];
__device__ __align__(256) __nv_bfloat16 gWdT_h[(size_t)DI * DTR];
__device__ __align__(256) __nv_bfloat16 gWdT_l[(size_t)DI * DTR];

// ---------------------------------------------------------------------------
// PTX helpers (sm_90 BASELINE only)
// ---------------------------------------------------------------------------
__device__ __forceinline__ uint32_t smem_u32(const void* p) {
    uint32_t a;
    asm("{ .reg .u64 t; cvta.to.shared.u64 t, %1; cvt.u32.u64 %0, t; }"
        : "=r"(a) : "l"(p));
    return a;
}
__device__ __forceinline__ void bulk_g2s(uint32_t dst, const void* src,
                                         uint32_t bytes, uint32_t mbar) {
    asm volatile(
        "cp.async.bulk.shared::cta.global.mbarrier::complete_tx::bytes "
        "[%0], [%1], %2, [%3];"
        :: "r"(dst), "l"(src), "r"(bytes), "r"(mbar) : "memory");
}
#define MBARRIER_INIT(mb, c) \
    asm volatile("mbarrier.init.shared.b64 [%0], %1;" :: "r"((uint32_t)(mb)), "r"((uint32_t)(c)) : "memory")
#define MBARRIER_INVAL(mb) \
    asm volatile("mbarrier.inval.shared.b64 [%0];" :: "r"((uint32_t)(mb)) : "memory")
#define MBARRIER_EXPECT_TX(mb, tx) \
    asm volatile("mbarrier.arrive.expect_tx.shared.b64 _, [%0], %1;" :: "r"((uint32_t)(mb)), "r"((uint32_t)(tx)) : "memory")

__device__ __forceinline__ void mbar_wait(uint32_t mb, uint32_t parity) {
    uint32_t done;
    asm volatile("{\n\t.reg .pred p;\n\t"
                 "mbarrier.try_wait.parity.acquire.cta.shared::cta.b64 p, [%1], %2;\n\t"
                 "selp.b32 %0, 1, 0, p;\n\t}"
                 : "=r"(done) : "r"(mb), "r"(parity) : "memory");
    if (!done) {
        asm volatile("{\n\t.reg .pred P1;\n\t"
                     "W%=:\n\t"
                     "mbarrier.try_wait.parity.acquire.cta.shared::cta.b64 P1, [%0], %1, 0x989680;\n\t"
                     "@P1 bra.uni D%=;\n\t"
                     "bra.uni W%=;\n\t"
                     "D%=:\n\t}" :: "r"(mb), "r"(parity) : "memory");
    }
}
__device__ __forceinline__ void ldmat_x4(uint32_t* r, uint32_t addr) {
    asm volatile("ldmatrix.sync.aligned.m8n8.x4.shared.b16 {%0,%1,%2,%3}, [%4];"
        : "=r"(r[0]), "=r"(r[1]), "=r"(r[2]), "=r"(r[3]) : "r"(addr));
}
__device__ __forceinline__ void mma16816(float* c, const uint32_t* a, const uint32_t* b) {
    asm volatile(
        "mma.sync.aligned.m16n8k16.row.col.f32.bf16.bf16.f32 "
        "{%0,%1,%2,%3}, {%4,%5,%6,%7}, {%8,%9}, {%0,%1,%2,%3};"
        : "+f"(c[0]), "+f"(c[1]), "+f"(c[2]), "+f"(c[3])
        : "r"(a[0]), "r"(a[1]), "r"(a[2]), "r"(a[3]), "r"(b[0]), "r"(b[1]));
}

// SW64 swizzle inside a 128x32 tile, byte offset
__device__ __forceinline__ uint32_t tile_off(int row, int k) {
    return (uint32_t)(row * 64) + (((uint32_t)(k * 2)) ^ (((uint32_t)(row >> 1) & 3u) << 4));
}
__device__ __forceinline__ float softplusf(float x) {
    return fmaxf(x, 0.f) + log1pf(__expf(-fabsf(x)));
}

// ---------------------------------------------------------------------------
// bf16 3-split HMMA GEMM, bulk-copy pipeline, occ 2.
// EPI=0: plain fp32 store. EPI=1: softplus(acc + bias[col]) store.
// ---------------------------------------------------------------------------
template <int EPI>
__global__ __launch_bounds__(256, 2) void tgemm_bulk(
    const __nv_bfloat16* __restrict__ Ah, const __nv_bfloat16* __restrict__ Al,
    const __nv_bfloat16* __restrict__ Bh, const __nv_bfloat16* __restrict__ Bl,
    float* __restrict__ C, int ldc, int Nvalid, int nkTot, int nkPer, size_t cslice,
    const float* __restrict__ bias)
{
    extern __shared__ char sm[];
    __shared__ uint64_t mbars[NSTAGE];
    const uint32_t smb = smem_u32(sm);
    const uint32_t mb0 = smem_u32(&mbars[0]);

    const int tid = threadIdx.x;
    const int wid = tid >> 5, lane = tid & 31;
    const int wy = wid & 3, wx = wid >> 2;
    const int g = lane >> 2, q2 = (lane & 3) * 2;
    const int mTile = blockIdx.y, nTile = blockIdx.x;
    const int kcB = blockIdx.z * nkPer;
    C += (size_t)blockIdx.z * cslice;

    const int laneA_row = (((lane >> 3) & 1) << 3) + (lane & 7);
    const uint32_t cA = ((lane >> 4) & 1) << 4;
    const uint32_t xorA = (((uint32_t)(laneA_row >> 1)) & 3u) << 4;
    const int laneB_row = (((lane >> 4) & 1) << 3) + (lane & 7);
    const uint32_t cB = ((lane >> 3) & 1) << 4;
    const uint32_t xorB = (((uint32_t)(laneB_row >> 1)) & 3u) << 4;
    const uint32_t aRow = (uint32_t)(wy * 32 + laneA_row) * 64;
    const uint32_t bRow = (uint32_t)(wx * 64 + laneB_row) * 64;

    if (tid == 0) {
#pragma unroll
        for (int s = 0; s < NSTAGE; ++s) MBARRIER_INIT(mb0 + 8 * s, 1);
    }
    __syncthreads();

    float acc[2][8][4];
#pragma unroll
    for (int mi = 0; mi < 2; ++mi)
#pragma unroll
        for (int ni = 0; ni < 8; ++ni)
#pragma unroll
            for (int j = 0; j < 4; ++j) acc[mi][ni][j] = 0.f;

    auto issue = [&](int c, int s) {
        const uint32_t sb = smb + (uint32_t)s * STAGE_BYTES;
        const uint32_t mb = mb0 + 8 * s;
        const size_t kc = (size_t)(kcB + c);
        const size_t aOff = ((size_t)mTile * nkTot + kc) * (TILE_BYTES / 2);
        const size_t bOff = ((size_t)nTile * nkTot + kc) * (TILE_BYTES / 2);
        MBARRIER_EXPECT_TX(mb, STAGE_BYTES);
        bulk_g2s(sb,          Ah + aOff, TILE_BYTES, mb);
        bulk_g2s(sb + OFF_AL, Al + aOff, TILE_BYTES, mb);
        bulk_g2s(sb + OFF_BH, Bh + bOff, TILE_BYTES, mb);
        bulk_g2s(sb + OFF_BL, Bl + bOff, TILE_BYTES, mb);
    };

    if (tid == 0) {
        issue(0, 0);
        if (nkPer > 1) issue(1, 1);
    }

    for (int c = 0; c < nkPer; ++c) {
        const int st = c % NSTAGE;
        if (tid == 0 && c + 2 < nkPer) issue(c + 2, (c + 2) % NSTAGE);
        mbar_wait(mb0 + 8 * st, (uint32_t)((c / NSTAGE) & 1));

        const uint32_t sb = smb + (uint32_t)st * STAGE_BYTES;
#pragma unroll
        for (int kk = 0; kk < 2; ++kk) {
            const uint32_t colA = ((uint32_t)(kk * 32) + cA) ^ xorA;
            const uint32_t colB = ((uint32_t)(kk * 32) + cB) ^ xorB;
            uint32_t ah[2][4], al[2][4];
#pragma unroll
            for (int mi = 0; mi < 2; ++mi) {
                const uint32_t mo = (uint32_t)(mi * 16 * 64);
                ldmat_x4(ah[mi], sb + aRow + mo + colA);
                ldmat_x4(al[mi], sb + OFF_AL + aRow + mo + colA);
            }
#pragma unroll
            for (int nip = 0; nip < 4; ++nip) {
                const uint32_t no = (uint32_t)(nip * 16 * 64);
                uint32_t bh[4], bl[4];
                ldmat_x4(bh, sb + OFF_BH + bRow + no + colB);
                ldmat_x4(bl, sb + OFF_BL + bRow + no + colB);
#pragma unroll
                for (int mi = 0; mi < 2; ++mi) {
                    mma16816(acc[mi][2 * nip],     ah[mi], bh);
                    mma16816(acc[mi][2 * nip],     al[mi], bh);
                    mma16816(acc[mi][2 * nip],     ah[mi], bl);
                    mma16816(acc[mi][2 * nip + 1], ah[mi], bh + 2);
                    mma16816(acc[mi][2 * nip + 1], al[mi], bh + 2);
                    mma16816(acc[mi][2 * nip + 1], ah[mi], bl + 2);
                }
            }
        }
        __syncthreads();
    }

    // epilogue
#pragma unroll
    for (int mi = 0; mi < 2; ++mi) {
        const int row = mTile * 128 + wy * 32 + mi * 16 + g;
#pragma unroll
        for (int ni = 0; ni < 8; ++ni) {
            const int col = nTile * 128 + wx * 64 + ni * 8 + q2;
            if (col < Nvalid) {
                float v0 = acc[mi][ni][0], v1 = acc[mi][ni][1];
                float v2 = acc[mi][ni][2], v3 = acc[mi][ni][3];
                if (EPI == 1) {
                    const float b0 = bias[col], b1 = bias[col + 1];
                    v0 = softplusf(v0 + b0); v1 = softplusf(v1 + b1);
                    v2 = softplusf(v2 + b0); v3 = softplusf(v3 + b1);
                }
                *(float2*)&C[(size_t)row * ldc + col] = make_float2(v0, v1);
                *(float2*)&C[(size_t)(row + 8) * ldc + col] = make_float2(v2, v3);
            }
        }
    }
    __syncthreads();
    if (tid == 0) {
#pragma unroll
        for (int s = 0; s < NSTAGE; ++s) MBARRIER_INVAL(mb0 + 8 * s);
    }
}

// ---------------------------------------------------------------------------
// reduce split-K partials; also emit bf16 hi/lo tiles of the dt columns
// ---------------------------------------------------------------------------
__global__ void reduce_proj_kernel() {
    const size_t i = (size_t)blockIdx.x * blockDim.x + threadIdx.x;
    if (i >= (size_t)MROWS * NPROJ) return;
    float s = 0.f;
#pragma unroll
    for (int z = 0; z < KSPLIT; ++z)
        s += g_projp[(size_t)z * MROWS * NPROJ + i];
    g_proj[i] = s;
    const int m = (int)(i / NPROJ), c = (int)(i % NPROJ);
    if (c < DTR) {
        const __nv_bfloat16 h = __float2bfloat16(s);
        const __nv_bfloat16 l = __float2bfloat16(s - __bfloat162float(h));
        const size_t tile = (size_t)(m >> 7) * 2 + (c >> 5);
        const uint32_t off = tile_off(m & 127, c & 31);
        *(__nv_bfloat16*)((char*)gdt_h + tile * TILE_BYTES + off) = h;
        *(__nv_bfloat16*)((char*)gdt_l + tile * TILE_BYTES + off) = l;
    }
}

// ---------------------------------------------------------------------------
// x -> tiled/swizzled bf16 hi/lo, float4 path (4 k per thread)
// ---------------------------------------------------------------------------
__global__ void split_x_kernel(const float* __restrict__ x)
{
    const size_t i4 = (size_t)blockIdx.x * blockDim.x + threadIdx.x;
    if (i4 >= (size_t)MROWS * DM / 4) return;
    const size_t idx = i4 * 4;
    const int m = (int)(idx / DM), k = (int)(idx % DM);
    const float4 v = *(const float4*)(x + idx);
    __nv_bfloat16 h[4], l[4];
    const float vv[4] = {v.x, v.y, v.z, v.w};
#pragma unroll
    for (int j = 0; j < 4; ++j) {
        h[j] = __float2bfloat16(vv[j]);
        l[j] = __float2bfloat16(vv[j] - __bfloat162float(h[j]));
    }
    const size_t tile = (size_t)(m >> 7) * NKC_DM + (k >> 5);
    const uint32_t off = tile_off(m & 127, k & 31);
    *(uint2*)((char*)gx_h + tile * TILE_BYTES + off) = *(uint2*)h;
    *(uint2*)((char*)gx_l + tile * TILE_BYTES + off) = *(uint2*)l;
}

// ---------------------------------------------------------------------------
// weight transpose+split: src [K][N] fp32 -> [nt][nkTot][128][32]
// 256 threads; phase 2 handles 4 consecutive k per thread (uint2 stores).
// ---------------------------------------------------------------------------
__global__ __launch_bounds__(256) void tsplit_kernel(
    const float* __restrict__ src, __nv_bfloat16* __restrict__ hi,
    __nv_bfloat16* __restrict__ lo, int K, int N, int nkTot)
{
    __shared__ float tile[32][33];
    const int n0 = blockIdx.x * 32, k0 = blockIdx.y * 32;
#pragma unroll
    for (int it = 0; it < 4; ++it) {
        const int idx = threadIdx.x + it * 256;
        const int ty = idx >> 5, tx = idx & 31;
        tile[ty][tx] = src[(size_t)(k0 + ty) * N + n0 + tx];
    }
    __syncthreads();
    const int n_loc = threadIdx.x & 31;
    const int kq = threadIdx.x >> 5;       // 0..7
    const int k_loc = kq * 4;
    const int n = n0 + n_loc, k = k0 + k_loc;
    __nv_bfloat16 h[4], l[4];
#pragma unroll
    for (int j = 0; j < 4; ++j) {
        const float v = tile[k_loc + j][n_loc];
        h[j] = __float2bfloat16(v);
        l[j] = __float2bfloat16(v - __bfloat162float(h[j]));
    }
    const size_t t = (size_t)(n >> 7) * nkTot + (k >> 5);
    const uint32_t off = tile_off(n & 127, k & 31);
    *(uint2*)((char*)hi + t * TILE_BYTES + off) = *(uint2*)h;
    *(uint2*)((char*)lo + t * TILE_BYTES + off) = *(uint2*)l;
}

// ---------------------------------------------------------------------------
// Causal conv1d (k=4) + SiLU, t-blocked: each thread computes 4 t x 4 d.
// ---------------------------------------------------------------------------
#define NDG (DI/4)    // 512 d-groups
__global__ void conv_silu_kernel(const float* __restrict__ cw,
                                 const float* __restrict__ cb)
{
    const size_t i = (size_t)blockIdx.x * blockDim.x + threadIdx.x;
    if (i >= (size_t)(MROWS / 4) * NDG) return;
    const int dg = (int)(i % NDG), tg = (int)(i / NDG);
    const int d = dg * 4;
    const int m0 = tg * 4;
    const int t0 = m0 % TLEN;

    const float4 b4 = *(const float4*)(cb + d);
    float4 w[4];
#pragma unroll
    for (int j = 0; j < 4; ++j) w[j] = *(const float4*)(cw + (d + j) * 4);

    float4 u[7];
#pragma unroll
    for (int r = 0; r < 7; ++r) {
        const int tt = t0 - 3 + r;
        if (tt >= 0)
            u[r] = *(const float4*)(g_uz + (size_t)(m0 - 3 + r) * (2 * DI) + d);
        else
            u[r] = make_float4(0.f, 0.f, 0.f, 0.f);
    }

    const size_t tileB = ((size_t)(m0 >> 7) * NKC_DI + (d >> 5)) * TILE_BYTES;
#pragma unroll
    for (int lt = 0; lt < 4; ++lt) {
        float a[4] = { b4.x, b4.y, b4.z, b4.w };
#pragma unroll
        for (int k = 0; k < 4; ++k) {
            const float* ur = (const float*)&u[lt + k];
#pragma unroll
            for (int j = 0; j < 4; ++j)
                a[j] += ur[j] * ((const float*)&w[j])[k];
        }
        float v[4];
        __nv_bfloat16 h[4], l[4];
#pragma unroll
        for (int j = 0; j < 4; ++j) {
            v[j] = a[j] / (1.f + __expf(-a[j]));
            h[j] = __float2bfloat16(v[j]);
            l[j] = __float2bfloat16(v[j] - __bfloat162float(h[j]));
        }
        *(float4*)(g_uc + (size_t)(m0 + lt) * DI + d) =
            make_float4(v[0], v[1], v[2], v[3]);
        const uint32_t off = tile_off((m0 + lt) & 127, d & 31);
        *(uint2*)((char*)guc_h + tileB + off) = *(uint2*)h;
        *(uint2*)((char*)guc_l + tileB + off) = *(uint2*)l;
    }
}

// ---------------------------------------------------------------------------
// SSM scan, 16 lanes per d (1 state each). 256 threads = 16 d-channels,
// grid (DI/16, BSZ) = 256 CTAs (2048 warps -> 3.46 warps/SMSP latency hiding).
// ---------------------------------------------------------------------------
#define SCAN_TB 64
__global__ __launch_bounds__(256) void scan_kernel(
    const float* __restrict__ A_log, const float* __restrict__ Dp)
{
    const int b = blockIdx.y;
    const int tid = threadIdx.x;
    const int warp = tid >> 5;
    const int lane = tid & 31;
    const int d_sub = lane >> 4;       // 0..1
    const int n = lane & 15;           // 0..15
    const int d_local = warp * 2 + d_sub;   // 0..15
    const int d0 = blockIdx.x * 16;
    const int d = d0 + d_local;

    __shared__ float sDelta[SCAN_TB][17];
    __shared__ float sUc[SCAN_TB][17];
    __shared__ float sZ[SCAN_TB][17];
    __shared__ float sY[SCAN_TB][17];
    __shared__ float sB[SCAN_TB][NST];
    __shared__ float sC[SCAN_TB][NST];
    __shared__ float sD[16];

    if (tid < 16) sD[tid] = Dp[d0 + tid];

    const float A = -__expf(A_log[(size_t)d * NST + n]);
    float h = 0.f;

    for (int t0 = 0; t0 < TLEN; t0 += SCAN_TB) {
        __syncthreads();
        // stage-in: delta/uc/z (64 x 16), B/C (64 x 32)
#pragma unroll
        for (int p = 0; p < 4; ++p) {
            const int i = tid + p * 256;
            const int r = i >> 4, c = i & 15;
            const size_t row = (size_t)(b * TLEN + t0 + r);
            sDelta[r][c] = g_delta[row * DI + d0 + c];
            sUc[r][c]    = g_uc[row * DI + d0 + c];
            sZ[r][c]     = g_uz[row * (2 * DI) + DI + d0 + c];
        }
#pragma unroll
        for (int p = 0; p < 8; ++p) {
            const int i = tid + p * 256;
            const int r = i >> 5, cc = i & 31;
            const float v = g_proj[(size_t)(b * TLEN + t0 + r) * NPROJ + DTR + cc];
            if (cc < NST) sB[r][cc] = v;
            else          sC[r][cc - NST] = v;
        }
        __syncthreads();

#pragma unroll 4
        for (int tt = 0; tt < SCAN_TB; ++tt) {
            const float delta = sDelta[tt][d_local];
            const float du = delta * sUc[tt][d_local];
            h = __expf(delta * A) * h + du * sB[tt][n];
            float y = h * sC[tt][n];
            y += __shfl_xor_sync(0xffffffffu, y, 1);
            y += __shfl_xor_sync(0xffffffffu, y, 2);
            y += __shfl_xor_sync(0xffffffffu, y, 4);
            y += __shfl_xor_sync(0xffffffffu, y, 8);
            if (n == 0) sY[tt][d_local] = y;
        }
        __syncthreads();

        // epilogue: gate + skip + tiled bf16 split
#pragma unroll
        for (int p = 0; p < 4; ++p) {
            const int i = tid + p * 256;
            const int r = i >> 4, c = i & 15;
            const float uc = sUc[r][c];
            const float z = sZ[r][c];
            const float gate = z / (1.f + __expf(-z));
            const float v = (sY[r][c] + uc * sD[c]) * gate;
            const int m = b * TLEN + t0 + r;
            const int dd = d0 + c;
            const __nv_bfloat16 hh = __float2bfloat16(v);
            const __nv_bfloat16 ll = __float2bfloat16(v - __bfloat162float(hh));
            const size_t tile = (size_t)(m >> 7) * NKC_DI + (dd >> 5);
            const uint32_t off = tile_off(m & 127, dd & 31);
            *(__nv_bfloat16*)((char*)gy_h + tile * TILE_BYTES + off) = hh;
            *(__nv_bfloat16*)((char*)gy_l + tile * TILE_BYTES + off) = ll;
        }
    }
}

// ---------------------------------------------------------------------------
extern "C" void kernel_launch(void* const* d_in, const int* in_sizes, int n_in,
                              void* d_out, int out_size)
{
    const float* x      = (const float*)d_in[0];
    const float* W_in   = (const float*)d_in[1];
    const float* conv_w = (const float*)d_in[2];
    const float* conv_b = (const float*)d_in[3];
    const float* W_xprj = (const float*)d_in[4];
    const float* W_dt   = (const float*)d_in[5];
    const float* b_dt   = (const float*)d_in[6];
    const float* A_log  = (const float*)d_in[7];
    const float* Dp     = (const float*)d_in[8];
    const float* W_out  = (const float*)d_in[9];
    float* out = (float*)d_out;

    cudaFuncSetAttribute(tgemm_bulk<0>, cudaFuncAttributeMaxDynamicSharedMemorySize, TG_SMEM_BYTES);
    cudaFuncSetAttribute(tgemm_bulk<1>, cudaFuncAttributeMaxDynamicSharedMemorySize, TG_SMEM_BYTES);

    void *p_uz, *p_projp, *p_delta;
    void *p_xh, *p_xl, *p_WinTh, *p_WinTl, *p_uch, *p_ucl;
    void *p_WxTh, *p_WxTl, *p_yh, *p_yl, *p_WoTh, *p_WoTl;
    void *p_dth, *p_dtl, *p_WdTh, *p_WdTl;
    cudaGetSymbolAddress(&p_uz, g_uz);
    cudaGetSymbolAddress(&p_projp, g_projp);
    cudaGetSymbolAddress(&p_delta, g_delta);
    cudaGetSymbolAddress(&p_xh, gx_h);       cudaGetSymbolAddress(&p_xl, gx_l);
    cudaGetSymbolAddress(&p_WinTh, gWinT_h); cudaGetSymbolAddress(&p_WinTl, gWinT_l);
    cudaGetSymbolAddress(&p_uch, guc_h);     cudaGetSymbolAddress(&p_ucl, guc_l);
    cudaGetSymbolAddress(&p_WxTh, gWxT_h);   cudaGetSymbolAddress(&p_WxTl, gWxT_l);
    cudaGetSymbolAddress(&p_yh, gy_h);       cudaGetSymbolAddress(&p_yl, gy_l);
    cudaGetSymbolAddress(&p_WoTh, gWoT_h);   cudaGetSymbolAddress(&p_WoTl, gWoT_l);
    cudaGetSymbolAddress(&p_dth, gdt_h);     cudaGetSymbolAddress(&p_dtl, gdt_l);
    cudaGetSymbolAddress(&p_WdTh, gWdT_h);   cudaGetSymbolAddress(&p_WdTl, gWdT_l);

    // prep for GEMM1 only
    {
        size_t n4 = (size_t)MROWS * DM / 4;
        split_x_kernel<<<(unsigned)((n4 + 255) / 256), 256>>>(x);
    }
    tsplit_kernel<<<dim3((2 * DI) / 32, DM / 32), 256>>>(
        W_in, (__nv_bfloat16*)p_WinTh, (__nv_bfloat16*)p_WinTl, DM, 2 * DI, NKC_DM);

    // 1) xz = x @ W_in
    tgemm_bulk<0><<<dim3(32, 32, 1), 256, TG_SMEM_BYTES>>>(
        (const __nv_bfloat16*)p_xh, (const __nv_bfloat16*)p_xl,
        (const __nv_bfloat16*)p_WinTh, (const __nv_bfloat16*)p_WinTl,
        (float*)p_uz, 2 * DI, 2 * DI, NKC_DM, NKC_DM, 0, nullptr);

    // 2) conv + SiLU (t-blocked)
    {
        const size_t total = (size_t)(MROWS / 4) * NDG;
        conv_silu_kernel<<<(unsigned)((total + 255) / 256), 256>>>(conv_w, conv_b);
    }

    // 3) proj = uc @ W_xproj : split-K=8
    tsplit_kernel<<<dim3(NPROJ / 32, DI / 32), 256>>>(
        W_xprj, (__nv_bfloat16*)p_WxTh, (__nv_bfloat16*)p_WxTl, DI, NPROJ, NKC_DI);
    tgemm_bulk<0><<<dim3(1, 32, KSPLIT), 256, TG_SMEM_BYTES>>>(
        (const __nv_bfloat16*)p_uch, (const __nv_bfloat16*)p_ucl,
        (const __nv_bfloat16*)p_WxTh, (const __nv_bfloat16*)p_WxTl,
        (float*)p_projp, NPROJ, NPROJ, NKC_DI, NKC_DI / KSPLIT,
        (size_t)MROWS * NPROJ, nullptr);
    {
        const size_t total = (size_t)MROWS * NPROJ;
        reduce_proj_kernel<<<(unsigned)((total + 255) / 256), 256>>>();
    }

    // 4) delta = softplus(proj_dt @ W_dt + b_dt)
    tsplit_kernel<<<dim3(DI / 32, DTR / 32), 256>>>(
        W_dt, (__nv_bfloat16*)p_WdTh, (__nv_bfloat16*)p_WdTl, DTR, DI, 2);
    tgemm_bulk<1><<<dim3(DI / 128, 32, 1), 256, TG_SMEM_BYTES>>>(
        (const __nv_bfloat16*)p_dth, (const __nv_bfloat16*)p_dtl,
        (const __nv_bfloat16*)p_WdTh, (const __nv_bfloat16*)p_WdTl,
        (float*)p_delta, DI, DI, 2, 2, 0, b_dt);

    // 5) scan (16 lanes/d, 256 CTAs)
    scan_kernel<<<dim3(DI / 16, BSZ), 256>>>(A_log, Dp);

    // 6) out = y @ W_out
    tsplit_kernel<<<dim3(DM / 32, DI / 32), 256>>>(
        W_out, (__nv_bfloat16*)p_WoTh, (__nv_bfloat16*)p_WoTl, DI, DM, NKC_DI);
    tgemm_bulk<0><<<dim3(8, 32, 1), 256, TG_SMEM_BYTES>>>(
        (const __nv_bfloat16*)p_yh, (const __nv_bfloat16*)p_yl,
        (const __nv_bfloat16*)p_WoTh, (const __nv_bfloat16*)p_WoTl,
        out, DM, DM, NKC_DI, NKC_DI, 0, nullptr);
}

// round 16
// speedup vs baseline: 1.1438x; 1.0008x over previous
#include <cuda_runtime.h>
#include <cuda_bf16.h>
#include <cstdint>
#include <math.h>

// Problem constants
#define BSZ   2
#define TLEN  2048
#define DM    1024
#define DI    2048
#define NST   16
#define DTR   64
#define NPROJ 96
#define MROWS (BSZ*TLEN)    // 4096
#define KSPLIT 8

#define NKC_DM (DM/32)      // 32 k-chunks for K=1024
#define NKC_DI (DI/32)      // 64 k-chunks for K=2048

// Tiles: 128 rows x 32 k bf16 = 8KB, SW64-swizzled 64B rows.
#define TILE_BYTES 8192
#define STAGE_BYTES (4*TILE_BYTES)     // Ah|Al|Bh|Bl = 32KB
#define NSTAGE 3
#define TG_SMEM_BYTES (NSTAGE*STAGE_BYTES)  // 96KB

#define OFF_AL TILE_BYTES
#define OFF_BH (2*TILE_BYTES)
#define OFF_BL (3*TILE_BYTES)

// ---------------------------------------------------------------------------
// Scratch (device globals; zero-initialized — pad rows stay zero)
// ---------------------------------------------------------------------------
__device__ __align__(256) float g_uz[(size_t)MROWS * 2 * DI];
__device__ __align__(256) float g_uc[(size_t)MROWS * DI];
__device__ __align__(256) float g_proj[(size_t)MROWS * NPROJ];
__device__ __align__(256) float g_projp[(size_t)KSPLIT * MROWS * NPROJ];
__device__ __align__(256) float g_delta[(size_t)MROWS * DI];

// pre-tiled, pre-swizzled bf16 operands: 8KB tiles of [128 rows][32 k]
__device__ __align__(256) __nv_bfloat16 gx_h[(size_t)MROWS * DM];
__device__ __align__(256) __nv_bfloat16 gx_l[(size_t)MROWS * DM];
__device__ __align__(256) __nv_bfloat16 gWinT_h[(size_t)(2*DI) * DM];
__device__ __align__(256) __nv_bfloat16 gWinT_l[(size_t)(2*DI) * DM];
__device__ __align__(256) __nv_bfloat16 guc_h[(size_t)MROWS * DI];
__device__ __align__(256) __nv_bfloat16 guc_l[(size_t)MROWS * DI];
__device__ __align__(256) __nv_bfloat16 gWxT_h[(size_t)128 * DI];
__device__ __align__(256) __nv_bfloat16 gWxT_l[(size_t)128 * DI];
__device__ __align__(256) __nv_bfloat16 gy_h[(size_t)MROWS * DI];
__device__ __align__(256) __nv_bfloat16 gy_l[(size_t)MROWS * DI];
__device__ __align__(256) __nv_bfloat16 gWoT_h[(size_t)DM * DI];
__device__ __align__(256) __nv_bfloat16 gWoT_l[(size_t)DM * DI];
// dt GEMM operands
__device__ __align__(256) __nv_bfloat16 gdt_h[(size_t)MROWS * DTR];
__device__ __align__(256) __nv_bfloat16 gdt_l[(size_t)MROWS * DTR];
__device__ __align__(256) __nv_bfloat16 gWdT_h[(size_t)DI * DTR];
__device__ __align__(256) __nv_bfloat16 gWdT_l[(size_t)DI * DTR];

// ---------------------------------------------------------------------------
// PTX helpers (sm_90 BASELINE only)
// ---------------------------------------------------------------------------
__device__ __forceinline__ uint32_t smem_u32(const void* p) {
    uint32_t a;
    asm("{ .reg .u64 t; cvta.to.shared.u64 t, %1; cvt.u32.u64 %0, t; }"
        : "=r"(a) : "l"(p));
    return a;
}
__device__ __forceinline__ void bulk_g2s(uint32_t dst, const void* src,
                                         uint32_t bytes, uint32_t mbar) {
    asm volatile(
        "cp.async.bulk.shared::cta.global.mbarrier::complete_tx::bytes "
        "[%0], [%1], %2, [%3];"
        :: "r"(dst), "l"(src), "r"(bytes), "r"(mbar) : "memory");
}
#define MBARRIER_INIT(mb, c) \
    asm volatile("mbarrier.init.shared.b64 [%0], %1;" :: "r"((uint32_t)(mb)), "r"((uint32_t)(c)) : "memory")
#define MBARRIER_INVAL(mb) \
    asm volatile("mbarrier.inval.shared.b64 [%0];" :: "r"((uint32_t)(mb)) : "memory")
#define MBARRIER_EXPECT_TX(mb, tx) \
    asm volatile("mbarrier.arrive.expect_tx.shared.b64 _, [%0], %1;" :: "r"((uint32_t)(mb)), "r"((uint32_t)(tx)) : "memory")

__device__ __forceinline__ void mbar_wait(uint32_t mb, uint32_t parity) {
    uint32_t done;
    asm volatile("{\n\t.reg .pred p;\n\t"
                 "mbarrier.try_wait.parity.acquire.cta.shared::cta.b64 p, [%1], %2;\n\t"
                 "selp.b32 %0, 1, 0, p;\n\t}"
                 : "=r"(done) : "r"(mb), "r"(parity) : "memory");
    if (!done) {
        asm volatile("{\n\t.reg .pred P1;\n\t"
                     "W%=:\n\t"
                     "mbarrier.try_wait.parity.acquire.cta.shared::cta.b64 P1, [%0], %1, 0x989680;\n\t"
                     "@P1 bra.uni D%=;\n\t"
                     "bra.uni W%=;\n\t"
                     "D%=:\n\t}" :: "r"(mb), "r"(parity) : "memory");
    }
}
__device__ __forceinline__ void ldmat_x4(uint32_t* r, uint32_t addr) {
    asm volatile("ldmatrix.sync.aligned.m8n8.x4.shared.b16 {%0,%1,%2,%3}, [%4];"
        : "=r"(r[0]), "=r"(r[1]), "=r"(r[2]), "=r"(r[3]) : "r"(addr));
}
__device__ __forceinline__ void mma16816(float* c, const uint32_t* a, const uint32_t* b) {
    asm volatile(
        "mma.sync.aligned.m16n8k16.row.col.f32.bf16.bf16.f32 "
        "{%0,%1,%2,%3}, {%4,%5,%6,%7}, {%8,%9}, {%0,%1,%2,%3};"
        : "+f"(c[0]), "+f"(c[1]), "+f"(c[2]), "+f"(c[3])
        : "r"(a[0]), "r"(a[1]), "r"(a[2]), "r"(a[3]), "r"(b[0]), "r"(b[1]));
}

// SW64 swizzle inside a 128x32 tile, byte offset
__device__ __forceinline__ uint32_t tile_off(int row, int k) {
    return (uint32_t)(row * 64) + (((uint32_t)(k * 2)) ^ (((uint32_t)(row >> 1) & 3u) << 4));
}
__device__ __forceinline__ float softplusf(float x) {
    return fmaxf(x, 0.f) + log1pf(__expf(-fabsf(x)));
}

// ---------------------------------------------------------------------------
// bf16 3-split HMMA GEMM, bulk-copy pipeline, occ 2.
// Term-major MMA issue: per nip-pair, 3 passes of 8 MMAs over distinct
// accumulators -> same-acc reissue spacing 8 instrs (covers HMMA RAW latency).
// EPI=0: plain fp32 store. EPI=1: softplus(acc + bias[col]) store.
// ---------------------------------------------------------------------------
template <int EPI>
__global__ __launch_bounds__(256, 2) void tgemm_bulk(
    const __nv_bfloat16* __restrict__ Ah, const __nv_bfloat16* __restrict__ Al,
    const __nv_bfloat16* __restrict__ Bh, const __nv_bfloat16* __restrict__ Bl,
    float* __restrict__ C, int ldc, int Nvalid, int nkTot, int nkPer, size_t cslice,
    const float* __restrict__ bias)
{
    extern __shared__ char sm[];
    __shared__ uint64_t mbars[NSTAGE];
    const uint32_t smb = smem_u32(sm);
    const uint32_t mb0 = smem_u32(&mbars[0]);

    const int tid = threadIdx.x;
    const int wid = tid >> 5, lane = tid & 31;
    const int wy = wid & 3, wx = wid >> 2;
    const int g = lane >> 2, q2 = (lane & 3) * 2;
    const int mTile = blockIdx.y, nTile = blockIdx.x;
    const int kcB = blockIdx.z * nkPer;
    C += (size_t)blockIdx.z * cslice;

    const int laneA_row = (((lane >> 3) & 1) << 3) + (lane & 7);
    const uint32_t cA = ((lane >> 4) & 1) << 4;
    const uint32_t xorA = (((uint32_t)(laneA_row >> 1)) & 3u) << 4;
    const int laneB_row = (((lane >> 4) & 1) << 3) + (lane & 7);
    const uint32_t cB = ((lane >> 3) & 1) << 4;
    const uint32_t xorB = (((uint32_t)(laneB_row >> 1)) & 3u) << 4;
    const uint32_t aRow = (uint32_t)(wy * 32 + laneA_row) * 64;
    const uint32_t bRow = (uint32_t)(wx * 64 + laneB_row) * 64;

    if (tid == 0) {
#pragma unroll
        for (int s = 0; s < NSTAGE; ++s) MBARRIER_INIT(mb0 + 8 * s, 1);
    }
    __syncthreads();

    float acc[2][8][4];
#pragma unroll
    for (int mi = 0; mi < 2; ++mi)
#pragma unroll
        for (int ni = 0; ni < 8; ++ni)
#pragma unroll
            for (int j = 0; j < 4; ++j) acc[mi][ni][j] = 0.f;

    auto issue = [&](int c, int s) {
        const uint32_t sb = smb + (uint32_t)s * STAGE_BYTES;
        const uint32_t mb = mb0 + 8 * s;
        const size_t kc = (size_t)(kcB + c);
        const size_t aOff = ((size_t)mTile * nkTot + kc) * (TILE_BYTES / 2);
        const size_t bOff = ((size_t)nTile * nkTot + kc) * (TILE_BYTES / 2);
        MBARRIER_EXPECT_TX(mb, STAGE_BYTES);
        bulk_g2s(sb,          Ah + aOff, TILE_BYTES, mb);
        bulk_g2s(sb + OFF_AL, Al + aOff, TILE_BYTES, mb);
        bulk_g2s(sb + OFF_BH, Bh + bOff, TILE_BYTES, mb);
        bulk_g2s(sb + OFF_BL, Bl + bOff, TILE_BYTES, mb);
    };

    if (tid == 0) {
        issue(0, 0);
        if (nkPer > 1) issue(1, 1);
    }

    for (int c = 0; c < nkPer; ++c) {
        const int st = c % NSTAGE;
        if (tid == 0 && c + 2 < nkPer) issue(c + 2, (c + 2) % NSTAGE);
        mbar_wait(mb0 + 8 * st, (uint32_t)((c / NSTAGE) & 1));

        const uint32_t sb = smb + (uint32_t)st * STAGE_BYTES;
#pragma unroll
        for (int kk = 0; kk < 2; ++kk) {
            const uint32_t colA = ((uint32_t)(kk * 32) + cA) ^ xorA;
            const uint32_t colB = ((uint32_t)(kk * 32) + cB) ^ xorB;
            uint32_t ah[2][4], al[2][4];
#pragma unroll
            for (int mi = 0; mi < 2; ++mi) {
                const uint32_t mo = (uint32_t)(mi * 16 * 64);
                ldmat_x4(ah[mi], sb + aRow + mo + colA);
                ldmat_x4(al[mi], sb + OFF_AL + aRow + mo + colA);
            }
            // nip pairs; term-major issue within each pair (8 distinct accs)
#pragma unroll
            for (int half = 0; half < 2; ++half) {
                uint32_t bh[2][4], bl[2][4];
#pragma unroll
                for (int pi = 0; pi < 2; ++pi) {
                    const uint32_t no = (uint32_t)((2 * half + pi) * 16 * 64);
                    ldmat_x4(bh[pi], sb + OFF_BH + bRow + no + colB);
                    ldmat_x4(bl[pi], sb + OFF_BL + bRow + no + colB);
                }
                // pass 1: Ah * Bh (8 MMAs, distinct accumulators)
#pragma unroll
                for (int pi = 0; pi < 2; ++pi)
#pragma unroll
                    for (int sub = 0; sub < 2; ++sub)
#pragma unroll
                        for (int mi = 0; mi < 2; ++mi)
                            mma16816(acc[mi][4 * half + 2 * pi + sub],
                                     ah[mi], bh[pi] + 2 * sub);
                // pass 2: Al * Bh
#pragma unroll
                for (int pi = 0; pi < 2; ++pi)
#pragma unroll
                    for (int sub = 0; sub < 2; ++sub)
#pragma unroll
                        for (int mi = 0; mi < 2; ++mi)
                            mma16816(acc[mi][4 * half + 2 * pi + sub],
                                     al[mi], bh[pi] + 2 * sub);
                // pass 3: Ah * Bl
#pragma unroll
                for (int pi = 0; pi < 2; ++pi)
#pragma unroll
                    for (int sub = 0; sub < 2; ++sub)
#pragma unroll
                        for (int mi = 0; mi < 2; ++mi)
                            mma16816(acc[mi][4 * half + 2 * pi + sub],
                                     ah[mi], bl[pi] + 2 * sub);
            }
        }
        __syncthreads();
    }

    // epilogue
#pragma unroll
    for (int mi = 0; mi < 2; ++mi) {
        const int row = mTile * 128 + wy * 32 + mi * 16 + g;
#pragma unroll
        for (int ni = 0; ni < 8; ++ni) {
            const int col = nTile * 128 + wx * 64 + ni * 8 + q2;
            if (col < Nvalid) {
                float v0 = acc[mi][ni][0], v1 = acc[mi][ni][1];
                float v2 = acc[mi][ni][2], v3 = acc[mi][ni][3];
                if (EPI == 1) {
                    const float b0 = bias[col], b1 = bias[col + 1];
                    v0 = softplusf(v0 + b0); v1 = softplusf(v1 + b1);
                    v2 = softplusf(v2 + b0); v3 = softplusf(v3 + b1);
                }
                *(float2*)&C[(size_t)row * ldc + col] = make_float2(v0, v1);
                *(float2*)&C[(size_t)(row + 8) * ldc + col] = make_float2(v2, v3);
            }
        }
    }
    __syncthreads();
    if (tid == 0) {
#pragma unroll
        for (int s = 0; s < NSTAGE; ++s) MBARRIER_INVAL(mb0 + 8 * s);
    }
}

// ---------------------------------------------------------------------------
// reduce split-K partials; also emit bf16 hi/lo tiles of the dt columns
// ---------------------------------------------------------------------------
__global__ void reduce_proj_kernel() {
    const size_t i = (size_t)blockIdx.x * blockDim.x + threadIdx.x;
    if (i >= (size_t)MROWS * NPROJ) return;
    float s = 0.f;
#pragma unroll
    for (int z = 0; z < KSPLIT; ++z)
        s += g_projp[(size_t)z * MROWS * NPROJ + i];
    g_proj[i] = s;
    const int m = (int)(i / NPROJ), c = (int)(i % NPROJ);
    if (c < DTR) {
        const __nv_bfloat16 h = __float2bfloat16(s);
        const __nv_bfloat16 l = __float2bfloat16(s - __bfloat162float(h));
        const size_t tile = (size_t)(m >> 7) * 2 + (c >> 5);
        const uint32_t off = tile_off(m & 127, c & 31);
        *(__nv_bfloat16*)((char*)gdt_h + tile * TILE_BYTES + off) = h;
        *(__nv_bfloat16*)((char*)gdt_l + tile * TILE_BYTES + off) = l;
    }
}

// ---------------------------------------------------------------------------
// x -> tiled/swizzled bf16 hi/lo, float4 path (4 k per thread)
// ---------------------------------------------------------------------------
__global__ void split_x_kernel(const float* __restrict__ x)
{
    const size_t i4 = (size_t)blockIdx.x * blockDim.x + threadIdx.x;
    if (i4 >= (size_t)MROWS * DM / 4) return;
    const size_t idx = i4 * 4;
    const int m = (int)(idx / DM), k = (int)(idx % DM);
    const float4 v = *(const float4*)(x + idx);
    __nv_bfloat16 h[4], l[4];
    const float vv[4] = {v.x, v.y, v.z, v.w};
#pragma unroll
    for (int j = 0; j < 4; ++j) {
        h[j] = __float2bfloat16(vv[j]);
        l[j] = __float2bfloat16(vv[j] - __bfloat162float(h[j]));
    }
    const size_t tile = (size_t)(m >> 7) * NKC_DM + (k >> 5);
    const uint32_t off = tile_off(m & 127, k & 31);
    *(uint2*)((char*)gx_h + tile * TILE_BYTES + off) = *(uint2*)h;
    *(uint2*)((char*)gx_l + tile * TILE_BYTES + off) = *(uint2*)l;
}

// ---------------------------------------------------------------------------
// weight transpose+split: src [K][N] fp32 -> [nt][nkTot][128][32]
// 256 threads; phase 2 handles 4 consecutive k per thread (uint2 stores).
// ---------------------------------------------------------------------------
__global__ __launch_bounds__(256) void tsplit_kernel(
    const float* __restrict__ src, __nv_bfloat16* __restrict__ hi,
    __nv_bfloat16* __restrict__ lo, int K, int N, int nkTot)
{
    __shared__ float tile[32][33];
    const int n0 = blockIdx.x * 32, k0 = blockIdx.y * 32;
#pragma unroll
    for (int it = 0; it < 4; ++it) {
        const int idx = threadIdx.x + it * 256;
        const int ty = idx >> 5, tx = idx & 31;
        tile[ty][tx] = src[(size_t)(k0 + ty) * N + n0 + tx];
    }
    __syncthreads();
    const int n_loc = threadIdx.x & 31;
    const int kq = threadIdx.x >> 5;
    const int k_loc = kq * 4;
    const int n = n0 + n_loc, k = k0 + k_loc;
    __nv_bfloat16 h[4], l[4];
#pragma unroll
    for (int j = 0; j < 4; ++j) {
        const float v = tile[k_loc + j][n_loc];
        h[j] = __float2bfloat16(v);
        l[j] = __float2bfloat16(v - __bfloat162float(h[j]));
    }
    const size_t t = (size_t)(n >> 7) * nkTot + (k >> 5);
    const uint32_t off = tile_off(n & 127, k & 31);
    *(uint2*)((char*)hi + t * TILE_BYTES + off) = *(uint2*)h;
    *(uint2*)((char*)lo + t * TILE_BYTES + off) = *(uint2*)l;
}

// ---------------------------------------------------------------------------
// Causal conv1d (k=4) + SiLU, t-blocked: each thread computes 4 t x 4 d.
// ---------------------------------------------------------------------------
#define NDG (DI/4)    // 512 d-groups
__global__ void conv_silu_kernel(const float* __restrict__ cw,
                                 const float* __restrict__ cb)
{
    const size_t i = (size_t)blockIdx.x * blockDim.x + threadIdx.x;
    if (i >= (size_t)(MROWS / 4) * NDG) return;
    const int dg = (int)(i % NDG), tg = (int)(i / NDG);
    const int d = dg * 4;
    const int m0 = tg * 4;
    const int t0 = m0 % TLEN;

    const float4 b4 = *(const float4*)(cb + d);
    float4 w[4];
#pragma unroll
    for (int j = 0; j < 4; ++j) w[j] = *(const float4*)(cw + (d + j) * 4);

    float4 u[7];
#pragma unroll
    for (int r = 0; r < 7; ++r) {
        const int tt = t0 - 3 + r;
        if (tt >= 0)
            u[r] = *(const float4*)(g_uz + (size_t)(m0 - 3 + r) * (2 * DI) + d);
        else
            u[r] = make_float4(0.f, 0.f, 0.f, 0.f);
    }

    const size_t tileB = ((size_t)(m0 >> 7) * NKC_DI + (d >> 5)) * TILE_BYTES;
#pragma unroll
    for (int lt = 0; lt < 4; ++lt) {
        float a[4] = { b4.x, b4.y, b4.z, b4.w };
#pragma unroll
        for (int k = 0; k < 4; ++k) {
            const float* ur = (const float*)&u[lt + k];
#pragma unroll
            for (int j = 0; j < 4; ++j)
                a[j] += ur[j] * ((const float*)&w[j])[k];
        }
        float v[4];
        __nv_bfloat16 h[4], l[4];
#pragma unroll
        for (int j = 0; j < 4; ++j) {
            v[j] = a[j] / (1.f + __expf(-a[j]));
            h[j] = __float2bfloat16(v[j]);
            l[j] = __float2bfloat16(v[j] - __bfloat162float(h[j]));
        }
        *(float4*)(g_uc + (size_t)(m0 + lt) * DI + d) =
            make_float4(v[0], v[1], v[2], v[3]);
        const uint32_t off = tile_off((m0 + lt) & 127, d & 31);
        *(uint2*)((char*)guc_h + tileB + off) = *(uint2*)h;
        *(uint2*)((char*)guc_l + tileB + off) = *(uint2*)l;
    }
}

// ---------------------------------------------------------------------------
// SSM scan, 16 lanes per d (1 state each). 256 threads = 16 d-channels,
// grid (DI/16, BSZ) = 256 CTAs.
// ---------------------------------------------------------------------------
#define SCAN_TB 64
__global__ __launch_bounds__(256) void scan_kernel(
    const float* __restrict__ A_log, const float* __restrict__ Dp)
{
    const int b = blockIdx.y;
    const int tid = threadIdx.x;
    const int warp = tid >> 5;
    const int lane = tid & 31;
    const int d_sub = lane >> 4;
    const int n = lane & 15;
    const int d_local = warp * 2 + d_sub;
    const int d0 = blockIdx.x * 16;
    const int d = d0 + d_local;

    __shared__ float sDelta[SCAN_TB][17];
    __shared__ float sUc[SCAN_TB][17];
    __shared__ float sZ[SCAN_TB][17];
    __shared__ float sY[SCAN_TB][17];
    __shared__ float sB[SCAN_TB][NST];
    __shared__ float sC[SCAN_TB][NST];
    __shared__ float sD[16];

    if (tid < 16) sD[tid] = Dp[d0 + tid];

    const float A = -__expf(A_log[(size_t)d * NST + n]);
    float h = 0.f;

    for (int t0 = 0; t0 < TLEN; t0 += SCAN_TB) {
        __syncthreads();
#pragma unroll
        for (int p = 0; p < 4; ++p) {
            const int i = tid + p * 256;
            const int r = i >> 4, c = i & 15;
            const size_t row = (size_t)(b * TLEN + t0 + r);
            sDelta[r][c] = g_delta[row * DI + d0 + c];
            sUc[r][c]    = g_uc[row * DI + d0 + c];
            sZ[r][c]     = g_uz[row * (2 * DI) + DI + d0 + c];
        }
#pragma unroll
        for (int p = 0; p < 8; ++p) {
            const int i = tid + p * 256;
            const int r = i >> 5, cc = i & 31;
            const float v = g_proj[(size_t)(b * TLEN + t0 + r) * NPROJ + DTR + cc];
            if (cc < NST) sB[r][cc] = v;
            else          sC[r][cc - NST] = v;
        }
        __syncthreads();

#pragma unroll 4
        for (int tt = 0; tt < SCAN_TB; ++tt) {
            const float delta = sDelta[tt][d_local];
            const float du = delta * sUc[tt][d_local];
            h = __expf(delta * A) * h + du * sB[tt][n];
            float y = h * sC[tt][n];
            y += __shfl_xor_sync(0xffffffffu, y, 1);
            y += __shfl_xor_sync(0xffffffffu, y, 2);
            y += __shfl_xor_sync(0xffffffffu, y, 4);
            y += __shfl_xor_sync(0xffffffffu, y, 8);
            if (n == 0) sY[tt][d_local] = y;
        }
        __syncthreads();

#pragma unroll
        for (int p = 0; p < 4; ++p) {
            const int i = tid + p * 256;
            const int r = i >> 4, c = i & 15;
            const float uc = sUc[r][c];
            const float z = sZ[r][c];
            const float gate = z / (1.f + __expf(-z));
            const float v = (sY[r][c] + uc * sD[c]) * gate;
            const int m = b * TLEN + t0 + r;
            const int dd = d0 + c;
            const __nv_bfloat16 hh = __float2bfloat16(v);
            const __nv_bfloat16 ll = __float2bfloat16(v - __bfloat162float(hh));
            const size_t tile = (size_t)(m >> 7) * NKC_DI + (dd >> 5);
            const uint32_t off = tile_off(m & 127, dd & 31);
            *(__nv_bfloat16*)((char*)gy_h + tile * TILE_BYTES + off) = hh;
            *(__nv_bfloat16*)((char*)gy_l + tile * TILE_BYTES + off) = ll;
        }
    }
}

// ---------------------------------------------------------------------------
extern "C" void kernel_launch(void* const* d_in, const int* in_sizes, int n_in,
                              void* d_out, int out_size)
{
    const float* x      = (const float*)d_in[0];
    const float* W_in   = (const float*)d_in[1];
    const float* conv_w = (const float*)d_in[2];
    const float* conv_b = (const float*)d_in[3];
    const float* W_xprj = (const float*)d_in[4];
    const float* W_dt   = (const float*)d_in[5];
    const float* b_dt   = (const float*)d_in[6];
    const float* A_log  = (const float*)d_in[7];
    const float* Dp     = (const float*)d_in[8];
    const float* W_out  = (const float*)d_in[9];
    float* out = (float*)d_out;

    cudaFuncSetAttribute(tgemm_bulk<0>, cudaFuncAttributeMaxDynamicSharedMemorySize, TG_SMEM_BYTES);
    cudaFuncSetAttribute(tgemm_bulk<1>, cudaFuncAttributeMaxDynamicSharedMemorySize, TG_SMEM_BYTES);

    void *p_uz, *p_projp, *p_delta;
    void *p_xh, *p_xl, *p_WinTh, *p_WinTl, *p_uch, *p_ucl;
    void *p_WxTh, *p_WxTl, *p_yh, *p_yl, *p_WoTh, *p_WoTl;
    void *p_dth, *p_dtl, *p_WdTh, *p_WdTl;
    cudaGetSymbolAddress(&p_uz, g_uz);
    cudaGetSymbolAddress(&p_projp, g_projp);
    cudaGetSymbolAddress(&p_delta, g_delta);
    cudaGetSymbolAddress(&p_xh, gx_h);       cudaGetSymbolAddress(&p_xl, gx_l);
    cudaGetSymbolAddress(&p_WinTh, gWinT_h); cudaGetSymbolAddress(&p_WinTl, gWinT_l);
    cudaGetSymbolAddress(&p_uch, guc_h);     cudaGetSymbolAddress(&p_ucl, guc_l);
    cudaGetSymbolAddress(&p_WxTh, gWxT_h);   cudaGetSymbolAddress(&p_WxTl, gWxT_l);
    cudaGetSymbolAddress(&p_yh, gy_h);       cudaGetSymbolAddress(&p_yl, gy_l);
    cudaGetSymbolAddress(&p_WoTh, gWoT_h);   cudaGetSymbolAddress(&p_WoTl, gWoT_l);
    cudaGetSymbolAddress(&p_dth, gdt_h);     cudaGetSymbolAddress(&p_dtl, gdt_l);
    cudaGetSymbolAddress(&p_WdTh, gWdT_h);   cudaGetSymbolAddress(&p_WdTl, gWdT_l);

    // prep for GEMM1 only
    {
        size_t n4 = (size_t)MROWS * DM / 4;
        split_x_kernel<<<(unsigned)((n4 + 255) / 256), 256>>>(x);
    }
    tsplit_kernel<<<dim3((2 * DI) / 32, DM / 32), 256>>>(
        W_in, (__nv_bfloat16*)p_WinTh, (__nv_bfloat16*)p_WinTl, DM, 2 * DI, NKC_DM);

    // 1) xz = x @ W_in
    tgemm_bulk<0><<<dim3(32, 32, 1), 256, TG_SMEM_BYTES>>>(
        (const __nv_bfloat16*)p_xh, (const __nv_bfloat16*)p_xl,
        (const __nv_bfloat16*)p_WinTh, (const __nv_bfloat16*)p_WinTl,
        (float*)p_uz, 2 * DI, 2 * DI, NKC_DM, NKC_DM, 0, nullptr);

    // 2) conv + SiLU (t-blocked)
    {
        const size_t total = (size_t)(MROWS / 4) * NDG;
        conv_silu_kernel<<<(unsigned)((total + 255) / 256), 256>>>(conv_w, conv_b);
    }

    // 3) proj = uc @ W_xproj : split-K=8
    tsplit_kernel<<<dim3(NPROJ / 32, DI / 32), 256>>>(
        W_xprj, (__nv_bfloat16*)p_WxTh, (__nv_bfloat16*)p_WxTl, DI, NPROJ, NKC_DI);
    tgemm_bulk<0><<<dim3(1, 32, KSPLIT), 256, TG_SMEM_BYTES>>>(
        (const __nv_bfloat16*)p_uch, (const __nv_bfloat16*)p_ucl,
        (const __nv_bfloat16*)p_WxTh, (const __nv_bfloat16*)p_WxTl,
        (float*)p_projp, NPROJ, NPROJ, NKC_DI, NKC_DI / KSPLIT,
        (size_t)MROWS * NPROJ, nullptr);
    {
        const size_t total = (size_t)MROWS * NPROJ;
        reduce_proj_kernel<<<(unsigned)((total + 255) / 256), 256>>>();
    }

    // 4) delta = softplus(proj_dt @ W_dt + b_dt)
    tsplit_kernel<<<dim3(DI / 32, DTR / 32), 256>>>(
        W_dt, (__nv_bfloat16*)p_WdTh, (__nv_bfloat16*)p_WdTl, DTR, DI, 2);
    tgemm_bulk<1><<<dim3(DI / 128, 32, 1), 256, TG_SMEM_BYTES>>>(
        (const __nv_bfloat16*)p_dth, (const __nv_bfloat16*)p_dtl,
        (const __nv_bfloat16*)p_WdTh, (const __nv_bfloat16*)p_WdTl,
        (float*)p_delta, DI, DI, 2, 2, 0, b_dt);

    // 5) scan
    scan_kernel<<<dim3(DI / 16, BSZ), 256>>>(A_log, Dp);

    // 6) out = y @ W_out
    tsplit_kernel<<<dim3(DM / 32, DI / 32), 256>>>(
        W_out, (__nv_bfloat16*)p_WoTh, (__nv_bfloat16*)p_WoTl, DI, DM, NKC_DI);
    tgemm_bulk<0><<<dim3(8, 32, 1), 256, TG_SMEM_BYTES>>>(
        (const __nv_bfloat16*)p_yh, (const __nv_bfloat16*)p_yl,
        (const __nv_bfloat16*)p_WoTh, (const __nv_bfloat16*)p_WoTl,
        out, DM, DM, NKC_DI, NKC_DI, 0, nullptr);
}

// round 17
// speedup vs baseline: 1.3535x; 1.1833x over previous
#include <cuda_runtime.h>
#include <cuda_fp16.h>
#include <cstdint>
#include <math.h>

// Problem constants
#define BSZ   2
#define TLEN  2048
#define DM    1024
#define DI    2048
#define NST   16
#define DTR   64
#define NPROJ 96
#define MROWS (BSZ*TLEN)    // 4096
#define KSPLIT 8

#define NKC_DM (DM/32)      // 32 k-chunks for K=1024
#define NKC_DI (DI/32)      // 64 k-chunks for K=2048

// Tiles: 128 rows x 32 k fp16 = 8KB, SW64-swizzled 64B rows.
#define TILE_BYTES 8192
#define STAGE_BYTES (3*TILE_BYTES)     // Ah|Al|Bh = 24KB
#define NSTAGE 3
#define TG_SMEM_BYTES (NSTAGE*STAGE_BYTES)  // 72KB

#define OFF_AL TILE_BYTES
#define OFF_BH (2*TILE_BYTES)

// ---------------------------------------------------------------------------
// Scratch (device globals; zero-initialized — pad rows stay zero)
// ---------------------------------------------------------------------------
__device__ __align__(256) float g_uz[(size_t)MROWS * 2 * DI];
__device__ __align__(256) float g_uc[(size_t)MROWS * DI];
__device__ __align__(256) float g_proj[(size_t)MROWS * NPROJ];
__device__ __align__(256) float g_projp[(size_t)KSPLIT * MROWS * NPROJ];
__device__ __align__(256) float g_delta[(size_t)MROWS * DI];

// pre-tiled, pre-swizzled fp16 operands: 8KB tiles of [128 rows][32 k]
// Activations: hi+lo pair. Weights: single fp16.
__device__ __align__(256) __half gx_h[(size_t)MROWS * DM];
__device__ __align__(256) __half gx_l[(size_t)MROWS * DM];
__device__ __align__(256) __half gWinT_h[(size_t)(2*DI) * DM];
__device__ __align__(256) __half guc_h[(size_t)MROWS * DI];
__device__ __align__(256) __half guc_l[(size_t)MROWS * DI];
__device__ __align__(256) __half gWxT_h[(size_t)128 * DI];   // rows 96..127 zero
__device__ __align__(256) __half gy_h[(size_t)MROWS * DI];
__device__ __align__(256) __half gy_l[(size_t)MROWS * DI];
__device__ __align__(256) __half gWoT_h[(size_t)DM * DI];
__device__ __align__(256) __half gdt_h[(size_t)MROWS * DTR];
__device__ __align__(256) __half gdt_l[(size_t)MROWS * DTR];
__device__ __align__(256) __half gWdT_h[(size_t)DI * DTR];

// ---------------------------------------------------------------------------
// PTX helpers (sm_90 BASELINE only)
// ---------------------------------------------------------------------------
__device__ __forceinline__ uint32_t smem_u32(const void* p) {
    uint32_t a;
    asm("{ .reg .u64 t; cvta.to.shared.u64 t, %1; cvt.u32.u64 %0, t; }"
        : "=r"(a) : "l"(p));
    return a;
}
__device__ __forceinline__ void bulk_g2s(uint32_t dst, const void* src,
                                         uint32_t bytes, uint32_t mbar) {
    asm volatile(
        "cp.async.bulk.shared::cta.global.mbarrier::complete_tx::bytes "
        "[%0], [%1], %2, [%3];"
        :: "r"(dst), "l"(src), "r"(bytes), "r"(mbar) : "memory");
}
#define MBARRIER_INIT(mb, c) \
    asm volatile("mbarrier.init.shared.b64 [%0], %1;" :: "r"((uint32_t)(mb)), "r"((uint32_t)(c)) : "memory")
#define MBARRIER_INVAL(mb) \
    asm volatile("mbarrier.inval.shared.b64 [%0];" :: "r"((uint32_t)(mb)) : "memory")
#define MBARRIER_EXPECT_TX(mb, tx) \
    asm volatile("mbarrier.arrive.expect_tx.shared.b64 _, [%0], %1;" :: "r"((uint32_t)(mb)), "r"((uint32_t)(tx)) : "memory")

__device__ __forceinline__ void mbar_wait(uint32_t mb, uint32_t parity) {
    uint32_t done;
    asm volatile("{\n\t.reg .pred p;\n\t"
                 "mbarrier.try_wait.parity.acquire.cta.shared::cta.b64 p, [%1], %2;\n\t"
                 "selp.b32 %0, 1, 0, p;\n\t}"
                 : "=r"(done) : "r"(mb), "r"(parity) : "memory");
    if (!done) {
        asm volatile("{\n\t.reg .pred P1;\n\t"
                     "W%=:\n\t"
                     "mbarrier.try_wait.parity.acquire.cta.shared::cta.b64 P1, [%0], %1, 0x989680;\n\t"
                     "@P1 bra.uni D%=;\n\t"
                     "bra.uni W%=;\n\t"
                     "D%=:\n\t}" :: "r"(mb), "r"(parity) : "memory");
    }
}
__device__ __forceinline__ void ldmat_x4(uint32_t* r, uint32_t addr) {
    asm volatile("ldmatrix.sync.aligned.m8n8.x4.shared.b16 {%0,%1,%2,%3}, [%4];"
        : "=r"(r[0]), "=r"(r[1]), "=r"(r[2]), "=r"(r[3]) : "r"(addr));
}
__device__ __forceinline__ void mma16816(float* c, const uint32_t* a, const uint32_t* b) {
    asm volatile(
        "mma.sync.aligned.m16n8k16.row.col.f32.f16.f16.f32 "
        "{%0,%1,%2,%3}, {%4,%5,%6,%7}, {%8,%9}, {%0,%1,%2,%3};"
        : "+f"(c[0]), "+f"(c[1]), "+f"(c[2]), "+f"(c[3])
        : "r"(a[0]), "r"(a[1]), "r"(a[2]), "r"(a[3]), "r"(b[0]), "r"(b[1]));
}

// SW64 swizzle inside a 128x32 tile, byte offset
__device__ __forceinline__ uint32_t tile_off(int row, int k) {
    return (uint32_t)(row * 64) + (((uint32_t)(k * 2)) ^ (((uint32_t)(row >> 1) & 3u) << 4));
}
__device__ __forceinline__ float softplusf(float x) {
    return fmaxf(x, 0.f) + log1pf(__expf(-fabsf(x)));
}
__device__ __forceinline__ void split_h(float v, __half& h, __half& l) {
    h = __float2half_rn(v);
    l = __float2half_rn(v - __half2float(h));
}

// ---------------------------------------------------------------------------
// fp16 2-term HMMA GEMM (A = Ah+Al activations, B single fp16 weights).
// C = (Ah + Al) * B^T. Bulk-copy pipeline, occ 2.
// EPI=0: plain fp32 store. EPI=1: softplus(acc + bias[col]) store.
// ---------------------------------------------------------------------------
template <int EPI>
__global__ __launch_bounds__(256, 2) void tgemm_bulk(
    const __half* __restrict__ Ah, const __half* __restrict__ Al,
    const __half* __restrict__ Bh,
    float* __restrict__ C, int ldc, int Nvalid, int nkTot, int nkPer, size_t cslice,
    const float* __restrict__ bias)
{
    extern __shared__ char sm[];
    __shared__ uint64_t mbars[NSTAGE];
    const uint32_t smb = smem_u32(sm);
    const uint32_t mb0 = smem_u32(&mbars[0]);

    const int tid = threadIdx.x;
    const int wid = tid >> 5, lane = tid & 31;
    const int wy = wid & 3, wx = wid >> 2;
    const int g = lane >> 2, q2 = (lane & 3) * 2;
    const int mTile = blockIdx.y, nTile = blockIdx.x;
    const int kcB = blockIdx.z * nkPer;
    C += (size_t)blockIdx.z * cslice;

    const int laneA_row = (((lane >> 3) & 1) << 3) + (lane & 7);
    const uint32_t cA = ((lane >> 4) & 1) << 4;
    const uint32_t xorA = (((uint32_t)(laneA_row >> 1)) & 3u) << 4;
    const int laneB_row = (((lane >> 4) & 1) << 3) + (lane & 7);
    const uint32_t cB = ((lane >> 3) & 1) << 4;
    const uint32_t xorB = (((uint32_t)(laneB_row >> 1)) & 3u) << 4;
    const uint32_t aRow = (uint32_t)(wy * 32 + laneA_row) * 64;
    const uint32_t bRow = (uint32_t)(wx * 64 + laneB_row) * 64;

    if (tid == 0) {
#pragma unroll
        for (int s = 0; s < NSTAGE; ++s) MBARRIER_INIT(mb0 + 8 * s, 1);
    }
    __syncthreads();

    float acc[2][8][4];
#pragma unroll
    for (int mi = 0; mi < 2; ++mi)
#pragma unroll
        for (int ni = 0; ni < 8; ++ni)
#pragma unroll
            for (int j = 0; j < 4; ++j) acc[mi][ni][j] = 0.f;

    auto issue = [&](int c, int s) {
        const uint32_t sb = smb + (uint32_t)s * STAGE_BYTES;
        const uint32_t mb = mb0 + 8 * s;
        const size_t kc = (size_t)(kcB + c);
        const size_t aOff = ((size_t)mTile * nkTot + kc) * (TILE_BYTES / 2);
        const size_t bOff = ((size_t)nTile * nkTot + kc) * (TILE_BYTES / 2);
        MBARRIER_EXPECT_TX(mb, STAGE_BYTES);
        bulk_g2s(sb,          Ah + aOff, TILE_BYTES, mb);
        bulk_g2s(sb + OFF_AL, Al + aOff, TILE_BYTES, mb);
        bulk_g2s(sb + OFF_BH, Bh + bOff, TILE_BYTES, mb);
    };

    if (tid == 0) {
        issue(0, 0);
        if (nkPer > 1) issue(1, 1);
    }

    for (int c = 0; c < nkPer; ++c) {
        const int st = c % NSTAGE;
        if (tid == 0 && c + 2 < nkPer) issue(c + 2, (c + 2) % NSTAGE);
        mbar_wait(mb0 + 8 * st, (uint32_t)((c / NSTAGE) & 1));

        const uint32_t sb = smb + (uint32_t)st * STAGE_BYTES;
#pragma unroll
        for (int kk = 0; kk < 2; ++kk) {
            const uint32_t colA = ((uint32_t)(kk * 32) + cA) ^ xorA;
            const uint32_t colB = ((uint32_t)(kk * 32) + cB) ^ xorB;
            uint32_t ah[2][4], al[2][4];
#pragma unroll
            for (int mi = 0; mi < 2; ++mi) {
                const uint32_t mo = (uint32_t)(mi * 16 * 64);
                ldmat_x4(ah[mi], sb + aRow + mo + colA);
                ldmat_x4(al[mi], sb + OFF_AL + aRow + mo + colA);
            }
#pragma unroll
            for (int nip = 0; nip < 4; ++nip) {
                const uint32_t no = (uint32_t)(nip * 16 * 64);
                uint32_t bh[4];
                ldmat_x4(bh, sb + OFF_BH + bRow + no + colB);
#pragma unroll
                for (int mi = 0; mi < 2; ++mi) {
                    mma16816(acc[mi][2 * nip],     ah[mi], bh);
                    mma16816(acc[mi][2 * nip],     al[mi], bh);
                    mma16816(acc[mi][2 * nip + 1], ah[mi], bh + 2);
                    mma16816(acc[mi][2 * nip + 1], al[mi], bh + 2);
                }
            }
        }
        __syncthreads();
    }

    // epilogue
#pragma unroll
    for (int mi = 0; mi < 2; ++mi) {
        const int row = mTile * 128 + wy * 32 + mi * 16 + g;
#pragma unroll
        for (int ni = 0; ni < 8; ++ni) {
            const int col = nTile * 128 + wx * 64 + ni * 8 + q2;
            if (col < Nvalid) {
                float v0 = acc[mi][ni][0], v1 = acc[mi][ni][1];
                float v2 = acc[mi][ni][2], v3 = acc[mi][ni][3];
                if (EPI == 1) {
                    const float b0 = bias[col], b1 = bias[col + 1];
                    v0 = softplusf(v0 + b0); v1 = softplusf(v1 + b1);
                    v2 = softplusf(v2 + b0); v3 = softplusf(v3 + b1);
                }
                *(float2*)&C[(size_t)row * ldc + col] = make_float2(v0, v1);
                *(float2*)&C[(size_t)(row + 8) * ldc + col] = make_float2(v2, v3);
            }
        }
    }
    __syncthreads();
    if (tid == 0) {
#pragma unroll
        for (int s = 0; s < NSTAGE; ++s) MBARRIER_INVAL(mb0 + 8 * s);
    }
}

// ---------------------------------------------------------------------------
// reduce split-K partials; also emit fp16 hi/lo tiles of the dt columns
// ---------------------------------------------------------------------------
__global__ void reduce_proj_kernel() {
    const size_t i = (size_t)blockIdx.x * blockDim.x + threadIdx.x;
    if (i >= (size_t)MROWS * NPROJ) return;
    float s = 0.f;
#pragma unroll
    for (int z = 0; z < KSPLIT; ++z)
        s += g_projp[(size_t)z * MROWS * NPROJ + i];
    g_proj[i] = s;
    const int m = (int)(i / NPROJ), c = (int)(i % NPROJ);
    if (c < DTR) {
        __half h, l;
        split_h(s, h, l);
        const size_t tile = (size_t)(m >> 7) * 2 + (c >> 5);
        const uint32_t off = tile_off(m & 127, c & 31);
        *(__half*)((char*)gdt_h + tile * TILE_BYTES + off) = h;
        *(__half*)((char*)gdt_l + tile * TILE_BYTES + off) = l;
    }
}

// ---------------------------------------------------------------------------
// x -> tiled/swizzled fp16 hi/lo, float4 path (4 k per thread)
// ---------------------------------------------------------------------------
__global__ void split_x_kernel(const float* __restrict__ x)
{
    const size_t i4 = (size_t)blockIdx.x * blockDim.x + threadIdx.x;
    if (i4 >= (size_t)MROWS * DM / 4) return;
    const size_t idx = i4 * 4;
    const int m = (int)(idx / DM), k = (int)(idx % DM);
    const float4 v = *(const float4*)(x + idx);
    __half h[4], l[4];
    const float vv[4] = {v.x, v.y, v.z, v.w};
#pragma unroll
    for (int j = 0; j < 4; ++j) split_h(vv[j], h[j], l[j]);
    const size_t tile = (size_t)(m >> 7) * NKC_DM + (k >> 5);
    const uint32_t off = tile_off(m & 127, k & 31);
    *(uint2*)((char*)gx_h + tile * TILE_BYTES + off) = *(uint2*)h;
    *(uint2*)((char*)gx_l + tile * TILE_BYTES + off) = *(uint2*)l;
}

// ---------------------------------------------------------------------------
// weight transpose: src [K][N] fp32 -> single fp16 [nt][nkTot][128][32]
// ---------------------------------------------------------------------------
__global__ __launch_bounds__(256) void tsplit_kernel(
    const float* __restrict__ src, __half* __restrict__ hi,
    int K, int N, int nkTot)
{
    __shared__ float tile[32][33];
    const int n0 = blockIdx.x * 32, k0 = blockIdx.y * 32;
#pragma unroll
    for (int it = 0; it < 4; ++it) {
        const int idx = threadIdx.x + it * 256;
        const int ty = idx >> 5, tx = idx & 31;
        tile[ty][tx] = src[(size_t)(k0 + ty) * N + n0 + tx];
    }
    __syncthreads();
    const int n_loc = threadIdx.x & 31;
    const int kq = threadIdx.x >> 5;
    const int k_loc = kq * 4;
    const int n = n0 + n_loc, k = k0 + k_loc;
    __half h[4];
#pragma unroll
    for (int j = 0; j < 4; ++j)
        h[j] = __float2half_rn(tile[k_loc + j][n_loc]);
    const size_t t = (size_t)(n >> 7) * nkTot + (k >> 5);
    const uint32_t off = tile_off(n & 127, k & 31);
    *(uint2*)((char*)hi + t * TILE_BYTES + off) = *(uint2*)h;
}

// ---------------------------------------------------------------------------
// Causal conv1d (k=4) + SiLU, t-blocked: each thread computes 4 t x 4 d.
// ---------------------------------------------------------------------------
#define NDG (DI/4)    // 512 d-groups
__global__ void conv_silu_kernel(const float* __restrict__ cw,
                                 const float* __restrict__ cb)
{
    const size_t i = (size_t)blockIdx.x * blockDim.x + threadIdx.x;
    if (i >= (size_t)(MROWS / 4) * NDG) return;
    const int dg = (int)(i % NDG), tg = (int)(i / NDG);
    const int d = dg * 4;
    const int m0 = tg * 4;
    const int t0 = m0 % TLEN;

    const float4 b4 = *(const float4*)(cb + d);
    float4 w[4];
#pragma unroll
    for (int j = 0; j < 4; ++j) w[j] = *(const float4*)(cw + (d + j) * 4);

    float4 u[7];
#pragma unroll
    for (int r = 0; r < 7; ++r) {
        const int tt = t0 - 3 + r;
        if (tt >= 0)
            u[r] = *(const float4*)(g_uz + (size_t)(m0 - 3 + r) * (2 * DI) + d);
        else
            u[r] = make_float4(0.f, 0.f, 0.f, 0.f);
    }

    const size_t tileB = ((size_t)(m0 >> 7) * NKC_DI + (d >> 5)) * TILE_BYTES;
#pragma unroll
    for (int lt = 0; lt < 4; ++lt) {
        float a[4] = { b4.x, b4.y, b4.z, b4.w };
#pragma unroll
        for (int k = 0; k < 4; ++k) {
            const float* ur = (const float*)&u[lt + k];
#pragma unroll
            for (int j = 0; j < 4; ++j)
                a[j] += ur[j] * ((const float*)&w[j])[k];
        }
        float v[4];
        __half h[4], l[4];
#pragma unroll
        for (int j = 0; j < 4; ++j) {
            v[j] = a[j] / (1.f + __expf(-a[j]));
            split_h(v[j], h[j], l[j]);
        }
        *(float4*)(g_uc + (size_t)(m0 + lt) * DI + d) =
            make_float4(v[0], v[1], v[2], v[3]);
        const uint32_t off = tile_off((m0 + lt) & 127, d & 31);
        *(uint2*)((char*)guc_h + tileB + off) = *(uint2*)h;
        *(uint2*)((char*)guc_l + tileB + off) = *(uint2*)l;
    }
}

// ---------------------------------------------------------------------------
// SSM scan, 16 lanes per d (1 state each). 256 threads = 16 d-channels,
// grid (DI/16, BSZ) = 256 CTAs.
// ---------------------------------------------------------------------------
#define SCAN_TB 64
__global__ __launch_bounds__(256) void scan_kernel(
    const float* __restrict__ A_log, const float* __restrict__ Dp)
{
    const int b = blockIdx.y;
    const int tid = threadIdx.x;
    const int warp = tid >> 5;
    const int lane = tid & 31;
    const int d_sub = lane >> 4;
    const int n = lane & 15;
    const int d_local = warp * 2 + d_sub;
    const int d0 = blockIdx.x * 16;
    const int d = d0 + d_local;

    __shared__ float sDelta[SCAN_TB][17];
    __shared__ float sUc[SCAN_TB][17];
    __shared__ float sZ[SCAN_TB][17];
    __shared__ float sY[SCAN_TB][17];
    __shared__ float sB[SCAN_TB][NST];
    __shared__ float sC[SCAN_TB][NST];
    __shared__ float sD[16];

    if (tid < 16) sD[tid] = Dp[d0 + tid];

    const float A = -__expf(A_log[(size_t)d * NST + n]);
    float h = 0.f;

    for (int t0 = 0; t0 < TLEN; t0 += SCAN_TB) {
        __syncthreads();
#pragma unroll
        for (int p = 0; p < 4; ++p) {
            const int i = tid + p * 256;
            const int r = i >> 4, c = i & 15;
            const size_t row = (size_t)(b * TLEN + t0 + r);
            sDelta[r][c] = g_delta[row * DI + d0 + c];
            sUc[r][c]    = g_uc[row * DI + d0 + c];
            sZ[r][c]     = g_uz[row * (2 * DI) + DI + d0 + c];
        }
#pragma unroll
        for (int p = 0; p < 8; ++p) {
            const int i = tid + p * 256;
            const int r = i >> 5, cc = i & 31;
            const float v = g_proj[(size_t)(b * TLEN + t0 + r) * NPROJ + DTR + cc];
            if (cc < NST) sB[r][cc] = v;
            else          sC[r][cc - NST] = v;
        }
        __syncthreads();

#pragma unroll 4
        for (int tt = 0; tt < SCAN_TB; ++tt) {
            const float delta = sDelta[tt][d_local];
            const float du = delta * sUc[tt][d_local];
            h = __expf(delta * A) * h + du * sB[tt][n];
            float y = h * sC[tt][n];
            y += __shfl_xor_sync(0xffffffffu, y, 1);
            y += __shfl_xor_sync(0xffffffffu, y, 2);
            y += __shfl_xor_sync(0xffffffffu, y, 4);
            y += __shfl_xor_sync(0xffffffffu, y, 8);
            if (n == 0) sY[tt][d_local] = y;
        }
        __syncthreads();

#pragma unroll
        for (int p = 0; p < 4; ++p) {
            const int i = tid + p * 256;
            const int r = i >> 4, c = i & 15;
            const float uc = sUc[r][c];
            const float z = sZ[r][c];
            const float gate = z / (1.f + __expf(-z));
            const float v = (sY[r][c] + uc * sD[c]) * gate;
            const int m = b * TLEN + t0 + r;
            const int dd = d0 + c;
            __half hh, ll;
            split_h(v, hh, ll);
            const size_t tile = (size_t)(m >> 7) * NKC_DI + (dd >> 5);
            const uint32_t off = tile_off(m & 127, dd & 31);
            *(__half*)((char*)gy_h + tile * TILE_BYTES + off) = hh;
            *(__half*)((char*)gy_l + tile * TILE_BYTES + off) = ll;
        }
    }
}

// ---------------------------------------------------------------------------
extern "C" void kernel_launch(void* const* d_in, const int* in_sizes, int n_in,
                              void* d_out, int out_size)
{
    const float* x      = (const float*)d_in[0];
    const float* W_in   = (const float*)d_in[1];
    const float* conv_w = (const float*)d_in[2];
    const float* conv_b = (const float*)d_in[3];
    const float* W_xprj = (const float*)d_in[4];
    const float* W_dt   = (const float*)d_in[5];
    const float* b_dt   = (const float*)d_in[6];
    const float* A_log  = (const float*)d_in[7];
    const float* Dp     = (const float*)d_in[8];
    const float* W_out  = (const float*)d_in[9];
    float* out = (float*)d_out;

    cudaFuncSetAttribute(tgemm_bulk<0>, cudaFuncAttributeMaxDynamicSharedMemorySize, TG_SMEM_BYTES);
    cudaFuncSetAttribute(tgemm_bulk<1>, cudaFuncAttributeMaxDynamicSharedMemorySize, TG_SMEM_BYTES);

    void *p_uz, *p_projp, *p_delta;
    void *p_xh, *p_xl, *p_WinTh, *p_uch, *p_ucl;
    void *p_WxTh, *p_yh, *p_yl, *p_WoTh;
    void *p_dth, *p_dtl, *p_WdTh;
    cudaGetSymbolAddress(&p_uz, g_uz);
    cudaGetSymbolAddress(&p_projp, g_projp);
    cudaGetSymbolAddress(&p_delta, g_delta);
    cudaGetSymbolAddress(&p_xh, gx_h);       cudaGetSymbolAddress(&p_xl, gx_l);
    cudaGetSymbolAddress(&p_WinTh, gWinT_h);
    cudaGetSymbolAddress(&p_uch, guc_h);     cudaGetSymbolAddress(&p_ucl, guc_l);
    cudaGetSymbolAddress(&p_WxTh, gWxT_h);
    cudaGetSymbolAddress(&p_yh, gy_h);       cudaGetSymbolAddress(&p_yl, gy_l);
    cudaGetSymbolAddress(&p_WoTh, gWoT_h);
    cudaGetSymbolAddress(&p_dth, gdt_h);     cudaGetSymbolAddress(&p_dtl, gdt_l);
    cudaGetSymbolAddress(&p_WdTh, gWdT_h);

    // all preps first (also places GEMM1 at ncu capture slot 6)
    {
        size_t n4 = (size_t)MROWS * DM / 4;
        split_x_kernel<<<(unsigned)((n4 + 255) / 256), 256>>>(x);
    }
    tsplit_kernel<<<dim3((2 * DI) / 32, DM / 32), 256>>>(
        W_in, (__half*)p_WinTh, DM, 2 * DI, NKC_DM);
    tsplit_kernel<<<dim3(NPROJ / 32, DI / 32), 256>>>(
        W_xprj, (__half*)p_WxTh, DI, NPROJ, NKC_DI);
    tsplit_kernel<<<dim3(DM / 32, DI / 32), 256>>>(
        W_out, (__half*)p_WoTh, DI, DM, NKC_DI);
    tsplit_kernel<<<dim3(DI / 32, DTR / 32), 256>>>(
        W_dt, (__half*)p_WdTh, DTR, DI, 2);

    // 1) xz = x @ W_in
    tgemm_bulk<0><<<dim3(32, 32, 1), 256, TG_SMEM_BYTES>>>(
        (const __half*)p_xh, (const __half*)p_xl, (const __half*)p_WinTh,
        (float*)p_uz, 2 * DI, 2 * DI, NKC_DM, NKC_DM, 0, nullptr);

    // 2) conv + SiLU (t-blocked)
    {
        const size_t total = (size_t)(MROWS / 4) * NDG;
        conv_silu_kernel<<<(unsigned)((total + 255) / 256), 256>>>(conv_w, conv_b);
    }

    // 3) proj = uc @ W_xproj : split-K=8
    tgemm_bulk<0><<<dim3(1, 32, KSPLIT), 256, TG_SMEM_BYTES>>>(
        (const __half*)p_uch, (const __half*)p_ucl, (const __half*)p_WxTh,
        (float*)p_projp, NPROJ, NPROJ, NKC_DI, NKC_DI / KSPLIT,
        (size_t)MROWS * NPROJ, nullptr);
    {
        const size_t total = (size_t)MROWS * NPROJ;
        reduce_proj_kernel<<<(unsigned)((total + 255) / 256), 256>>>();
    }

    // 4) delta = softplus(proj_dt @ W_dt + b_dt)
    tgemm_bulk<1><<<dim3(DI / 128, 32, 1), 256, TG_SMEM_BYTES>>>(
        (const __half*)p_dth, (const __half*)p_dtl, (const __half*)p_WdTh,
        (float*)p_delta, DI, DI, 2, 2, 0, b_dt);

    // 5) scan
    scan_kernel<<<dim3(DI / 16, BSZ), 256>>>(A_log, Dp);

    // 6) out = y @ W_out
    tgemm_bulk<0><<<dim3(8, 32, 1), 256, TG_SMEM_BYTES>>>(
        (const __half*)p_yh, (const __half*)p_yl, (const __half*)p_WoTh,
        out, DM, DM, NKC_DI, NKC_DI, 0, nullptr);
}